// round 10
// baseline (speedup 1.0000x reference)
#include <cuda_runtime.h>
#include <cuda_bf16.h>
#include <math.h>

#define Bb  2
#define Cc  128
#define Hh  256
#define Ww  510
#define WFD 256
#define HWD 130560   /* 256*510 */
#define BCD 256      /* Bb*Cc */

typedef unsigned int u32;
typedef unsigned long long u64;

__device__ __forceinline__ u64 pk2(float lo, float hi) {
    u64 r; asm("mov.b64 %0,{%1,%2};" : "=l"(r) : "f"(lo), "f"(hi)); return r;
}
__device__ __forceinline__ float2 up2(u64 v) {
    float2 r; asm("mov.b64 {%0,%1},%2;" : "=f"(r.x), "=f"(r.y) : "l"(v)); return r;
}
__device__ __forceinline__ u64 ffma2(u64 a, u64 b, u64 c) {
    u64 d; asm("fma.rn.f32x2 %0,%1,%2,%3;" : "=l"(d) : "l"(a), "l"(b), "l"(c)); return d;
}

// ---- tensor-core helpers -------------------------------------------------
__device__ __forceinline__ void mma_bf16(float* c, const u32* a, const u32* b) {
    asm("mma.sync.aligned.m16n8k16.row.col.f32.bf16.bf16.f32 "
        "{%0,%1,%2,%3},{%4,%5,%6,%7},{%8,%9},{%0,%1,%2,%3};"
        : "+f"(c[0]), "+f"(c[1]), "+f"(c[2]), "+f"(c[3])
        : "r"(a[0]), "r"(a[1]), "r"(a[2]), "r"(a[3]), "r"(b[0]), "r"(b[1]));
}
__device__ __forceinline__ void ldmA(u32* a, u32 addr) {
    asm volatile("ldmatrix.sync.aligned.m8n8.x4.shared.b16 {%0,%1,%2,%3},[%4];"
        : "=r"(a[0]), "=r"(a[1]), "=r"(a[2]), "=r"(a[3]) : "r"(addr));
}
__device__ __forceinline__ void ldmAT(u32* a, u32 addr) {
    asm volatile("ldmatrix.sync.aligned.m8n8.x4.trans.shared.b16 {%0,%1,%2,%3},[%4];"
        : "=r"(a[0]), "=r"(a[1]), "=r"(a[2]), "=r"(a[3]) : "r"(addr));
}
__device__ __forceinline__ void ldmB(u32* b, u32 addr) {
    asm volatile("ldmatrix.sync.aligned.m8n8.x2.shared.b16 {%0,%1},[%2];"
        : "=r"(b[0]), "=r"(b[1]) : "r"(addr));
}
__device__ __forceinline__ void ldmBT(u32* b, u32 addr) {
    asm volatile("ldmatrix.sync.aligned.m8n8.x2.trans.shared.b16 {%0,%1},[%2];"
        : "=r"(b[0]), "=r"(b[1]) : "r"(addr));
}
__device__ __forceinline__ u32 smaddr(const void* p) {
    return (u32)__cvta_generic_to_shared(p);
}
__device__ __forceinline__ void bsplit2(float a, float b, u32& hi, u32& lo) {
    __nv_bfloat16 ha = __float2bfloat16(a), hb = __float2bfloat16(b);
    hi = (u32)__bfloat16_as_ushort(ha) | ((u32)__bfloat16_as_ushort(hb) << 16);
    float ra = a - __bfloat162float(ha), rb = b - __bfloat162float(hb);
    __nv_bfloat16 la = __float2bfloat16(ra), lb = __float2bfloat16(rb);
    lo = (u32)__bfloat16_as_ushort(la) | ((u32)__bfloat16_as_ushort(lb) << 16);
}

// ---------------- scratch ----------------
__device__ float  d_yg [(size_t)BCD * HWD];
__device__ float  d_yx [(size_t)BCD * HWD];
__device__ float2 d_Fg [(size_t)BCD * Hh * WFD];
__device__ float2 d_Fx [(size_t)BCD * Hh * WFD];
__device__ float2 d_Gg [(size_t)BCD * Hh * WFD];
__device__ float2 d_Gx [(size_t)BCD * Hh * WFD];
__device__ float2 d_Sb [(size_t)BCD * WFD * WFD];
__device__ float2 d_Tb [(size_t)BCD * Hh * WFD];
__device__ float  d_rb [(size_t)BCD * HWD];
__device__ float  d_rsq[BCD * Hh];
__device__ float2 d_W256[256];
// mma-fragment-order DFT tables
__device__ u64 d_DwFrh[32768], d_DwFrl[32768], d_DwFih[32768], d_DwFil[32768];
__device__ u64 d_CwF1h[32768], d_CwF1l[32768], d_CwF2h[32768], d_CwF2l[32768];
// conv weight A-fragment tables: [wsel][{01h,01l,23h,23l}][ (mblk*8+kblk)*32+lane ]
__device__ u64 d_WF[2][4][2048];

__device__ __forceinline__ void sp_bits(float x, u32& hb, u32& lb) {
    __nv_bfloat16 h = __float2bfloat16(x);
    hb = (u32)__bfloat16_as_ushort(h);
    lb = (u32)__bfloat16_as_ushort(__float2bfloat16(x - __bfloat162float(h)));
}

// ---------------- table builder ----------------
__global__ void build_tables_kernel() {
    int idx = blockIdx.x * blockDim.x + threadIdx.x;
    int stride = gridDim.x * blockDim.x;
    float rsW = rsqrtf(510.0f);

    for (int i = idx; i < 32768; i += stride) {
        int lane = i & 31, kblk = (i >> 5) & 31, nblk = i >> 10;
        int v = nblk * 8 + (lane >> 2);
        u32 prh[2], prl[2], pih[2], pil[2];
#pragma unroll
        for (int reg = 0; reg < 2; reg++) {
            prh[reg] = prl[reg] = pih[reg] = pil[reg] = 0;
#pragma unroll
            for (int e = 0; e < 2; e++) {
                int w = kblk * 16 + (lane & 3) * 2 + e + reg * 8;
                float re = 0.f, im = 0.f;
                if (w < Ww) {
                    int m = (w * v) % Ww;
                    float s, c; sincospif(2.0f * (float)m / (float)Ww, &s, &c);
                    re = c * rsW; im = -s * rsW;
                }
                u32 hb, lb;
                sp_bits(re, hb, lb);
                prh[reg] |= hb << (16 * e); prl[reg] |= lb << (16 * e);
                sp_bits(im, hb, lb);
                pih[reg] |= hb << (16 * e); pil[reg] |= lb << (16 * e);
            }
        }
        d_DwFrh[i] = (u64)prh[0] | ((u64)prh[1] << 32);
        d_DwFrl[i] = (u64)prl[0] | ((u64)prl[1] << 32);
        d_DwFih[i] = (u64)pih[0] | ((u64)pih[1] << 32);
        d_DwFil[i] = (u64)pil[0] | ((u64)pil[1] << 32);
    }
    for (int i = idx; i < 32768; i += stride) {
        int lane = i & 31, kblk = (i >> 5) & 15, nblk = i >> 9;
        int w = nblk * 8 + (lane >> 2);
        u32 p1h[2], p1l[2], p2h[2], p2l[2];
#pragma unroll
        for (int reg = 0; reg < 2; reg++) {
            p1h[reg] = p1l[reg] = p2h[reg] = p2l[reg] = 0;
#pragma unroll
            for (int e = 0; e < 2; e++) {
                int v = kblk * 16 + (lane & 3) * 2 + e + reg * 8;
                float b1 = 0.f, b2 = 0.f;
                if (w < Ww) {
                    int m = (v * w) % Ww;
                    float s, c; sincospif(2.0f * (float)m / (float)Ww, &s, &c);
                    float sv = (v == 0 || v == 255) ? 1.0f : 2.0f;
                    b1 = sv * c * rsW; b2 = -sv * s * rsW;
                }
                u32 hb, lb;
                sp_bits(b1, hb, lb);
                p1h[reg] |= hb << (16 * e); p1l[reg] |= lb << (16 * e);
                sp_bits(b2, hb, lb);
                p2h[reg] |= hb << (16 * e); p2l[reg] |= lb << (16 * e);
            }
        }
        d_CwF1h[i] = (u64)p1h[0] | ((u64)p1h[1] << 32);
        d_CwF1l[i] = (u64)p1l[0] | ((u64)p1l[1] << 32);
        d_CwF2h[i] = (u64)p2h[0] | ((u64)p2h[1] << 32);
        d_CwF2l[i] = (u64)p2l[0] | ((u64)p2l[1] << 32);
    }
    for (int j = idx; j < 256; j += stride) {
        float s, c; sincospif(2.0f * (float)j / 256.0f, &s, &c);
        d_W256[j] = make_float2(c, -s);
    }
}

// ---------------- W pack: 128x128 -> A-fragment order (hi/lo) ----------------
__global__ void pack_w_kernel(const float* __restrict__ wg, const float* __restrict__ wx) {
    int t = blockIdx.x * blockDim.x + threadIdx.x;   // 0..4095
    if (t >= 4096) return;
    int wsel = t >> 11;
    int i = t & 2047;
    const float* W = wsel ? wx : wg;
    int lane = i & 31, kblk = (i >> 5) & 7, mblk = i >> 8;
    u32 qh[4], ql[4];
#pragma unroll
    for (int reg = 0; reg < 4; reg++) {
        int row = mblk * 16 + (lane >> 2) + 8 * (reg & 1);
        u32 hi = 0, lo = 0;
#pragma unroll
        for (int e = 0; e < 2; e++) {
            int k = kblk * 16 + (lane & 3) * 2 + e + 8 * (reg >> 1);
            float v = W[row * 128 + k];
            u32 hb, lb; sp_bits(v, hb, lb);
            hi |= hb << (16 * e); lo |= lb << (16 * e);
        }
        qh[reg] = hi; ql[reg] = lo;
    }
    d_WF[wsel][0][i] = (u64)qh[0] | ((u64)qh[1] << 32);
    d_WF[wsel][1][i] = (u64)ql[0] | ((u64)ql[1] << 32);
    d_WF[wsel][2][i] = (u64)qh[2] | ((u64)qh[3] << 32);
    d_WF[wsel][3][i] = (u64)ql[2] | ((u64)ql[3] << 32);
}

__device__ __forceinline__ float sigm(float v) { return 1.f / (1.f + expf(-v)); }

#define PIT  40
#define PITS 72
#define ASZ  (64 * PIT)
#define SSZ  (32 * PITS)

// ---------------- 1x1 conv — HMMA, W fragments direct from gmem ----------------
__global__ void __launch_bounds__(256, 2) conv_tc(
    const float* __restrict__ X, int wsel,
    const float* __restrict__ bias, float* __restrict__ Y)
{
    __shared__ __nv_bfloat16 sXh[2][SSZ], sXl[2][SSZ];
    int b = blockIdx.z;
    const float* Xb = X + (size_t)b * Cc * HWD;
    float* Yb = Y + (size_t)b * Cc * HWD;
    int n0 = blockIdx.x * 64, m0 = blockIdx.y * 64;
    int t = threadIdx.x, lane = t & 31, wid = t >> 5;
    int wm = (wid >> 2) * 32, wn = (wid & 3) * 16;
    int g = lane >> 2, tc4 = lane & 3;

    float acc[2][2][4];
#pragma unroll
    for (int i = 0; i < 2; i++)
#pragma unroll
        for (int j = 0; j < 2; j++)
#pragma unroll
            for (int q = 0; q < 4; q++) acc[i][j][q] = 0.f;

    int kB = (lane & 7) + ((lane >> 3) & 1) * 8;
    int scB = t & 31, srB = t >> 5;
    int mblk_base = (m0 + wm) >> 4;

    float2 xv[4];
#define CONV_LOAD(K0) { \
    _Pragma("unroll") \
    for (int i = 0; i < 4; i++) \
        xv[i] = *(const float2*)&Xb[(size_t)((K0) + srB + i * 8) * HWD + n0 + 2 * scB]; }
#define CONV_STORE(BF) { \
    _Pragma("unroll") \
    for (int i = 0; i < 4; i++) { \
        u32 hi, lo; bsplit2(xv[i].x, xv[i].y, hi, lo); \
        int so = (srB + i * 8) * PITS + 2 * scB; \
        *(u32*)&sXh[BF][so] = hi; *(u32*)&sXl[BF][so] = lo; \
    } }

    CONV_LOAD(0)
    CONV_STORE(0)
    __syncthreads();
    for (int it = 0; it < 4; it++) {
        int buf = it & 1;
        if (it < 3) CONV_LOAD((it + 1) * 32)
        u32 aXh = smaddr(sXh[buf]), aXl = smaddr(sXl[buf]);
#pragma unroll
        for (int ks = 0; ks < 2; ks++) {
            int kb = ks * 16;
            int kblk = it * 2 + ks;
            u32 ah[2][4], al[2][4];
#pragma unroll
            for (int tm = 0; tm < 2; tm++) {
                size_t bi = ((size_t)((mblk_base + tm) * 8 + kblk) << 5) + lane;
                u64 v;
                v = d_WF[wsel][0][bi]; ah[tm][0] = (u32)v; ah[tm][1] = (u32)(v >> 32);
                v = d_WF[wsel][2][bi]; ah[tm][2] = (u32)v; ah[tm][3] = (u32)(v >> 32);
                v = d_WF[wsel][1][bi]; al[tm][0] = (u32)v; al[tm][1] = (u32)(v >> 32);
                v = d_WF[wsel][3][bi]; al[tm][2] = (u32)v; al[tm][3] = (u32)(v >> 32);
            }
            u32 bh[2][2], bl[2][2];
#pragma unroll
            for (int tn = 0; tn < 2; tn++) {
                u32 off = ((kb + kB) * PITS + wn + 8 * tn) * 2;
                ldmBT(bh[tn], aXh + off);
                ldmBT(bl[tn], aXl + off);
            }
#pragma unroll
            for (int tm = 0; tm < 2; tm++)
#pragma unroll
                for (int tn = 0; tn < 2; tn++) {
                    mma_bf16(acc[tm][tn], ah[tm], bh[tn]);
                    mma_bf16(acc[tm][tn], ah[tm], bl[tn]);
                    mma_bf16(acc[tm][tn], al[tm], bh[tn]);
                }
        }
        if (it < 3) CONV_STORE(buf ^ 1)
        __syncthreads();
    }
#undef CONV_LOAD
#undef CONV_STORE
#pragma unroll
    for (int tm = 0; tm < 2; tm++)
#pragma unroll
        for (int tn = 0; tn < 2; tn++) {
            int r0 = m0 + wm + 16 * tm + g;
            int col = n0 + wn + 8 * tn + 2 * tc4;
            float bv0 = bias[r0], bv1 = bias[r0 + 8];
            *(float2*)&Yb[(size_t)r0 * HWD + col] =
                make_float2(acc[tm][tn][0] + bv0, acc[tm][tn][1] + bv0);
            *(float2*)&Yb[(size_t)(r0 + 8) * HWD + col] =
                make_float2(acc[tm][tn][2] + bv1, acc[tm][tn][3] + bv1);
        }
}

// ------- rfft along W — HMMA, B fragments prefetched one ks ahead -------
#define RFW_BFRAG(KB, Brh, Brl, Bih, Bil) { \
    _Pragma("unroll") \
    for (int tn = 0; tn < 2; tn++) { \
        size_t bi = ((size_t)((nblk0 + tn) * 32 + (KB)) << 5) + lane; \
        u64 v; \
        v = d_DwFrh[bi]; Brh[tn][0] = (u32)v; Brh[tn][1] = (u32)(v >> 32); \
        v = d_DwFrl[bi]; Brl[tn][0] = (u32)v; Brl[tn][1] = (u32)(v >> 32); \
        v = d_DwFih[bi]; Bih[tn][0] = (u32)v; Bih[tn][1] = (u32)(v >> 32); \
        v = d_DwFil[bi]; Bil[tn][0] = (u32)v; Bil[tn][1] = (u32)(v >> 32); \
    } }

__global__ void __launch_bounds__(256, 2) rfftw_tc(
    const float* __restrict__ Y, float2* __restrict__ F)
{
    __shared__ __nv_bfloat16 sAh[2][ASZ], sAl[2][ASZ];
    int bc = blockIdx.z;
    const float* A = Y + (size_t)bc * HWD;
    float2* Cp = F + (size_t)bc * Hh * WFD;
    int n0 = blockIdx.x * 64, m0 = blockIdx.y * 64;
    int t = threadIdx.x, lane = t & 31, wid = t >> 5;
    int wm = (wid >> 2) * 32, wn = (wid & 3) * 16;
    int g = lane >> 2, tc = lane & 3;

    float cre[2][2][4], cim[2][2][4];
#pragma unroll
    for (int i = 0; i < 2; i++)
#pragma unroll
        for (int j = 0; j < 2; j++)
#pragma unroll
            for (int q = 0; q < 4; q++) { cre[i][j][q] = 0.f; cim[i][j][q] = 0.f; }

    int lrA = lane & 15, lkA = (lane >> 4) * 8;
    int sc = t & 15, sr = t >> 4;
    int nblk0 = (n0 + wn) >> 3;

    float a0[4], a1[4];
#define RFW_LOAD(K0) { \
    _Pragma("unroll") \
    for (int i = 0; i < 4; i++) { \
        int r = sr + i * 16; int w = (K0) + 2 * sc; \
        if (w < Ww) { float2 t2 = *(const float2*)&A[(size_t)(m0 + r) * Ww + w]; \
                      a0[i] = t2.x; a1[i] = t2.y; } \
        else { a0[i] = 0.f; a1[i] = 0.f; } \
    } }
#define RFW_STORE(BF) { \
    _Pragma("unroll") \
    for (int i = 0; i < 4; i++) { \
        int so = (sr + i * 16) * PIT + 2 * sc; \
        u32 hi, lo; bsplit2(a0[i], a1[i], hi, lo); \
        *(u32*)&sAh[BF][so] = hi; *(u32*)&sAl[BF][so] = lo; \
    } }

    u32 B0rh[2][2], B0rl[2][2], B0ih[2][2], B0il[2][2];
    u32 B1rh[2][2], B1rl[2][2], B1ih[2][2], B1il[2][2];
    RFW_BFRAG(0, B0rh, B0rl, B0ih, B0il)

    RFW_LOAD(0)
    RFW_STORE(0)
    __syncthreads();
    for (int it = 0; it < 16; it++) {
        int buf = it & 1;
        if (it < 15) RFW_LOAD((it + 1) * 32)
        u32 aAh = smaddr(sAh[buf]), aAl = smaddr(sAl[buf]);

        // ks = 0: prefetch kblk it*2+1 into B1, compute with B0
        {
            int kn = it * 2 + 1;
            RFW_BFRAG(kn, B1rh, B1rl, B1ih, B1il)
            u32 ah[2][4], al[2][4];
#pragma unroll
            for (int tm = 0; tm < 2; tm++) {
                u32 off = ((wm + 16 * tm + lrA) * PIT + lkA) * 2;
                ldmA(ah[tm], aAh + off);
                ldmA(al[tm], aAl + off);
            }
#pragma unroll
            for (int tm = 0; tm < 2; tm++)
#pragma unroll
                for (int tn = 0; tn < 2; tn++) {
                    mma_bf16(cre[tm][tn], ah[tm], B0rh[tn]);
                    mma_bf16(cre[tm][tn], ah[tm], B0rl[tn]);
                    mma_bf16(cre[tm][tn], al[tm], B0rh[tn]);
                    mma_bf16(cim[tm][tn], ah[tm], B0ih[tn]);
                    mma_bf16(cim[tm][tn], ah[tm], B0il[tn]);
                    mma_bf16(cim[tm][tn], al[tm], B0ih[tn]);
                }
        }
        // ks = 1: prefetch kblk it*2+2 (next iter) into B0, compute with B1
        {
            int kn = it * 2 + 2; if (kn > 31) kn = 31;
            RFW_BFRAG(kn, B0rh, B0rl, B0ih, B0il)
            u32 ah[2][4], al[2][4];
#pragma unroll
            for (int tm = 0; tm < 2; tm++) {
                u32 off = ((wm + 16 * tm + lrA) * PIT + 16 + lkA) * 2;
                ldmA(ah[tm], aAh + off);
                ldmA(al[tm], aAl + off);
            }
#pragma unroll
            for (int tm = 0; tm < 2; tm++)
#pragma unroll
                for (int tn = 0; tn < 2; tn++) {
                    mma_bf16(cre[tm][tn], ah[tm], B1rh[tn]);
                    mma_bf16(cre[tm][tn], ah[tm], B1rl[tn]);
                    mma_bf16(cre[tm][tn], al[tm], B1rh[tn]);
                    mma_bf16(cim[tm][tn], ah[tm], B1ih[tn]);
                    mma_bf16(cim[tm][tn], ah[tm], B1il[tn]);
                    mma_bf16(cim[tm][tn], al[tm], B1ih[tn]);
                }
        }
        if (it < 15) RFW_STORE(buf ^ 1)
        __syncthreads();
    }
#undef RFW_LOAD
#undef RFW_STORE
#pragma unroll
    for (int tm = 0; tm < 2; tm++)
#pragma unroll
        for (int tn = 0; tn < 2; tn++) {
            int r0 = m0 + wm + 16 * tm + g;
            int col = n0 + wn + 8 * tn + 2 * tc;
            float4 v0 = make_float4(cre[tm][tn][0], cim[tm][tn][0], cre[tm][tn][1], cim[tm][tn][1]);
            *(float4*)&Cp[(size_t)r0 * WFD + col] = v0;
            float4 v1 = make_float4(cre[tm][tn][2], cim[tm][tn][2], cre[tm][tn][3], cim[tm][tn][3]);
            *(float4*)&Cp[(size_t)(r0 + 8) * WFD + col] = v1;
        }
}

// ------- irfft along W + residual — HMMA, B fragments prefetched ----
#define IRF_BFRAG(KB, B1h, B1l, B2h, B2l) { \
    _Pragma("unroll") \
    for (int tn = 0; tn < 2; tn++) { \
        size_t bi = ((size_t)((nblk0 + tn) * 16 + (KB)) << 5) + lane; \
        u64 v; \
        v = d_CwF1h[bi]; B1h[tn][0] = (u32)v; B1h[tn][1] = (u32)(v >> 32); \
        v = d_CwF1l[bi]; B1l[tn][0] = (u32)v; B1l[tn][1] = (u32)(v >> 32); \
        v = d_CwF2h[bi]; B2h[tn][0] = (u32)v; B2h[tn][1] = (u32)(v >> 32); \
        v = d_CwF2l[bi]; B2l[tn][0] = (u32)v; B2l[tn][1] = (u32)(v >> 32); \
    } }

__global__ void __launch_bounds__(256, 2) irfft_add_tc(
    const float2* __restrict__ T, const float* __restrict__ x, float* __restrict__ r)
{
    __shared__ __nv_bfloat16 sArh[2][ASZ], sArl[2][ASZ], sAih[2][ASZ], sAil[2][ASZ];
    int bc = blockIdx.z;
    const float2* Ap = T + (size_t)bc * 65536;
    int n0 = blockIdx.x * 64, m0 = blockIdx.y * 64;
    int t = threadIdx.x, lane = t & 31, wid = t >> 5;
    int wm = (wid >> 2) * 32, wn = (wid & 3) * 16;
    int g = lane >> 2, tc = lane & 3;

    float acc[2][2][4];
#pragma unroll
    for (int i = 0; i < 2; i++)
#pragma unroll
        for (int j = 0; j < 2; j++)
#pragma unroll
            for (int q = 0; q < 4; q++) acc[i][j][q] = 0.f;

    int lrA = lane & 15, lkA = (lane >> 4) * 8;
    int sc = t & 15, sr = t >> 4;
    int nblk0 = (n0 + wn) >> 3;

    float4 va[4];
#define IRF_LOAD(K0) { \
    _Pragma("unroll") \
    for (int i = 0; i < 4; i++) { \
        int rr = sr + i * 16; \
        va[i] = *(const float4*)&Ap[(size_t)(m0 + rr) * 256 + (K0) + 2 * sc]; \
    } }
#define IRF_STORE(BF) { \
    _Pragma("unroll") \
    for (int i = 0; i < 4; i++) { \
        int so = (sr + i * 16) * PIT + 2 * sc; \
        u32 hi, lo; \
        bsplit2(va[i].x, va[i].z, hi, lo); \
        *(u32*)&sArh[BF][so] = hi; *(u32*)&sArl[BF][so] = lo; \
        bsplit2(va[i].y, va[i].w, hi, lo); \
        *(u32*)&sAih[BF][so] = hi; *(u32*)&sAil[BF][so] = lo; \
    } }

    u32 B01h[2][2], B01l[2][2], B02h[2][2], B02l[2][2];
    u32 B11h[2][2], B11l[2][2], B12h[2][2], B12l[2][2];
    IRF_BFRAG(0, B01h, B01l, B02h, B02l)

    IRF_LOAD(0)
    IRF_STORE(0)
    __syncthreads();
    for (int it = 0; it < 8; it++) {
        int buf = it & 1;
        if (it < 7) IRF_LOAD((it + 1) * 32)
        u32 aArh = smaddr(sArh[buf]), aArl = smaddr(sArl[buf]);
        u32 aAih = smaddr(sAih[buf]), aAil = smaddr(sAil[buf]);

        // ks = 0
        {
            int kn = it * 2 + 1;
            IRF_BFRAG(kn, B11h, B11l, B12h, B12l)
            u32 arh[2][4], arl[2][4], aih[2][4], ail[2][4];
#pragma unroll
            for (int tm = 0; tm < 2; tm++) {
                u32 off = ((wm + 16 * tm + lrA) * PIT + lkA) * 2;
                ldmA(arh[tm], aArh + off);
                ldmA(arl[tm], aArl + off);
                ldmA(aih[tm], aAih + off);
                ldmA(ail[tm], aAil + off);
            }
#pragma unroll
            for (int tm = 0; tm < 2; tm++)
#pragma unroll
                for (int tn = 0; tn < 2; tn++) {
                    mma_bf16(acc[tm][tn], arh[tm], B01h[tn]);
                    mma_bf16(acc[tm][tn], arh[tm], B01l[tn]);
                    mma_bf16(acc[tm][tn], arl[tm], B01h[tn]);
                    mma_bf16(acc[tm][tn], aih[tm], B02h[tn]);
                    mma_bf16(acc[tm][tn], aih[tm], B02l[tn]);
                    mma_bf16(acc[tm][tn], ail[tm], B02h[tn]);
                }
        }
        // ks = 1
        {
            int kn = it * 2 + 2; if (kn > 15) kn = 15;
            IRF_BFRAG(kn, B01h, B01l, B02h, B02l)
            u32 arh[2][4], arl[2][4], aih[2][4], ail[2][4];
#pragma unroll
            for (int tm = 0; tm < 2; tm++) {
                u32 off = ((wm + 16 * tm + lrA) * PIT + 16 + lkA) * 2;
                ldmA(arh[tm], aArh + off);
                ldmA(arl[tm], aArl + off);
                ldmA(aih[tm], aAih + off);
                ldmA(ail[tm], aAil + off);
            }
#pragma unroll
            for (int tm = 0; tm < 2; tm++)
#pragma unroll
                for (int tn = 0; tn < 2; tn++) {
                    mma_bf16(acc[tm][tn], arh[tm], B11h[tn]);
                    mma_bf16(acc[tm][tn], arh[tm], B11l[tn]);
                    mma_bf16(acc[tm][tn], arl[tm], B11h[tn]);
                    mma_bf16(acc[tm][tn], aih[tm], B12h[tn]);
                    mma_bf16(acc[tm][tn], aih[tm], B12l[tn]);
                    mma_bf16(acc[tm][tn], ail[tm], B12h[tn]);
                }
        }
        if (it < 7) IRF_STORE(buf ^ 1)
        __syncthreads();
    }
#undef IRF_LOAD
#undef IRF_STORE
#pragma unroll
    for (int tm = 0; tm < 2; tm++)
#pragma unroll
        for (int tn = 0; tn < 2; tn++) {
            int col = n0 + wn + 8 * tn + 2 * tc;
            if (col < Ww) {
                int r0 = m0 + wm + 16 * tm + g;
                size_t i0 = (size_t)bc * HWD + (size_t)r0 * Ww + col;
                size_t i1 = i0 + (size_t)8 * Ww;
                float2 xv = *(const float2*)&x[i0];
                *(float2*)&r[i0] = make_float2(acc[tm][tn][0] + xv.x, acc[tm][tn][1] + xv.y);
                xv = *(const float2*)&x[i1];
                *(float2*)&r[i1] = make_float2(acc[tm][tn][2] + xv.x, acc[tm][tn][3] + xv.y);
            }
        }
}

// ---------------- 256-pt FFT along slow axis (4-step 16x16) ----------------
template<int INV, int FILT>
__global__ void __launch_bounds__(256) ffth_kernel(
    const float2* __restrict__ in, float2* __restrict__ out,
    const float2* __restrict__ filt)
{
    __shared__ float2 Xs[256][17];
    __shared__ float2 Ws[256];
    int bc = blockIdx.y;
    int v0 = blockIdx.x * 16;
    int tx = threadIdx.x;
    int ty = threadIdx.y;
    int t = ty * 16 + tx;
    const float2* inp = in + (size_t)bc * 65536 + v0;
    float2* outp = out + (size_t)bc * 65536 + v0;

    {
        float2 w = d_W256[t];
        if (INV) w.y = -w.y;
        Ws[t] = w;
    }
#pragma unroll
    for (int i = 0; i < 16; i++) {
        int h = i * 16 + ty;
        Xs[h][tx] = inp[(size_t)h * 256 + tx];
    }
    __syncthreads();

    float2 rr[16];
    {
        u64 tw[16];
#pragma unroll
        for (int n1 = 0; n1 < 16; n1++) {
            float2 w = Ws[(n1 * ty * 16) & 255];
            tw[n1] = pk2(w.x, w.y);
        }
#pragma unroll
        for (int n2 = 0; n2 < 16; n2++) {
            u64 accA = 0ull, accB = 0ull;
#pragma unroll
            for (int n1 = 0; n1 < 16; n1++) {
                float2 xv = Xs[16 * n1 + n2][tx];
                u64 xp = pk2(xv.x, xv.y);
                u64 xq = pk2(xv.y, xv.x);
                accA = ffma2(xp, tw[n1], accA);
                accB = ffma2(xq, tw[n1], accB);
            }
            float2 a = up2(accA), b = up2(accB);
            float ar = a.x - a.y, ai = b.x + b.y;
            float2 tm = Ws[(n2 * ty) & 255];
            rr[n2] = make_float2(ar * tm.x - ai * tm.y, ar * tm.y + ai * tm.x);
        }
    }
    __syncthreads();
#pragma unroll
    for (int n2 = 0; n2 < 16; n2++)
        Xs[ty * 16 + n2][tx] = rr[n2];
    __syncthreads();

    {
        u64 tw[16];
#pragma unroll
        for (int n2 = 0; n2 < 16; n2++) {
            float2 w = Ws[(n2 * ty * 16) & 255];
            tw[n2] = pk2(w.x, w.y);
        }
        int c = bc & (Cc - 1);
#pragma unroll
        for (int k1 = 0; k1 < 16; k1++) {
            u64 accA = 0ull, accB = 0ull;
#pragma unroll
            for (int n2 = 0; n2 < 16; n2++) {
                float2 xv = Xs[k1 * 16 + n2][tx];
                u64 xp = pk2(xv.x, xv.y);
                u64 xq = pk2(xv.y, xv.x);
                accA = ffma2(xp, tw[n2], accA);
                accB = ffma2(xq, tw[n2], accB);
            }
            float2 a = up2(accA), b = up2(accB);
            int u = k1 + 16 * ty;
            float2 v = make_float2((a.x - a.y) * 0.0625f, (b.x + b.y) * 0.0625f);
            if (FILT) {
                float2 wc = filt[((size_t)c * Hh + u) * WFD + v0 + tx];
                v = make_float2(v.x * wc.x - v.y * wc.y, v.x * wc.y + v.y * wc.x);
            }
            outp[(size_t)u * 256 + tx] = v;
        }
    }
}

// ------- variance over v per (bc,u) row -------
__global__ void var_kernel(const float2* __restrict__ G, float* __restrict__ rsq)
{
    __shared__ float s0[256], s1[256], s2[256];
    int row = blockIdx.x;
    int tid = threadIdx.x;
    float2 z = G[(size_t)row * WFD + tid];
    s0[tid] = z.x; s1[tid] = z.y; s2[tid] = z.x * z.x + z.y * z.y;
    __syncthreads();
    for (int s = 128; s > 0; s >>= 1) {
        if (tid < s) { s0[tid] += s0[tid + s]; s1[tid] += s1[tid + s]; s2[tid] += s2[tid + s]; }
        __syncthreads();
    }
    if (tid == 0) {
        float mr = s0[0] * (1.f / WFD), mi = s1[0] * (1.f / WFD);
        float var = s2[0] * (1.f / WFD) - (mr * mr + mi * mi);
        rsq[row] = 1.f / sqrtf(6.283185307179586f * var);
    }
}

// ------- scores — HMMA complex, double-buffered (dynamic smem) -------
__global__ void __launch_bounds__(256) scores_tc(
    const float2* __restrict__ Gb, const float2* __restrict__ Xb,
    const float* __restrict__ rsq, float2* __restrict__ Sb)
{
    extern __shared__ __nv_bfloat16 dynS[];
    __nv_bfloat16* sGrh = dynS;
    __nv_bfloat16* sGrl = sGrh + 2 * SSZ;
    __nv_bfloat16* sGih = sGrl + 2 * SSZ;
    __nv_bfloat16* sGil = sGih + 2 * SSZ;
    __nv_bfloat16* sXrh = sGil + 2 * SSZ;
    __nv_bfloat16* sXrl = sXrh + 2 * SSZ;
    __nv_bfloat16* sXih = sXrl + 2 * SSZ;
    __nv_bfloat16* sXil = sXih + 2 * SSZ;
    int bc = blockIdx.z;
    const float2* Ap = Gb + (size_t)bc * 65536;
    const float2* Bp = Xb + (size_t)bc * 65536;
    float2* Cp = Sb + (size_t)bc * 65536;
    int n0 = blockIdx.x * 64, m0 = blockIdx.y * 64;
    int t = threadIdx.x, lane = t & 31, wid = t >> 5;
    int wm = (wid >> 2) * 32, wn = (wid & 3) * 16;
    int g = lane >> 2, tc4 = lane & 3;

    float are[2][2][4], aim[2][2][4];
#pragma unroll
    for (int i = 0; i < 2; i++)
#pragma unroll
        for (int j = 0; j < 2; j++)
#pragma unroll
            for (int q = 0; q < 4; q++) { are[i][j][q] = 0.f; aim[i][j][q] = 0.f; }

    int kA = (lane & 7) + ((lane >> 4) & 1) * 8;
    int mA = ((lane >> 3) & 1) * 8;
    int kB = (lane & 7) + ((lane >> 3) & 1) * 8;
    int sc = t & 31, sr = t >> 5;

    float4 vA[4], vB[4];
#define SCR_LOAD(K0) { \
    _Pragma("unroll") \
    for (int i = 0; i < 4; i++) { \
        int k = sr + i * 8; \
        vA[i] = *(const float4*)&Ap[(size_t)((K0) + k) * 256 + m0 + 2 * sc]; \
        vB[i] = *(const float4*)&Bp[(size_t)((K0) + k) * 256 + n0 + 2 * sc]; \
    } }
#define SCR_STORE(BF) { \
    _Pragma("unroll") \
    for (int i = 0; i < 4; i++) { \
        int so = (BF) * SSZ + (sr + i * 8) * PITS + 2 * sc; \
        u32 hi, lo; \
        bsplit2(vA[i].x, vA[i].z, hi, lo); *(u32*)&sGrh[so] = hi; *(u32*)&sGrl[so] = lo; \
        bsplit2(vA[i].y, vA[i].w, hi, lo); *(u32*)&sGih[so] = hi; *(u32*)&sGil[so] = lo; \
        bsplit2(vB[i].x, vB[i].z, hi, lo); *(u32*)&sXrh[so] = hi; *(u32*)&sXrl[so] = lo; \
        bsplit2(vB[i].y, vB[i].w, hi, lo); *(u32*)&sXih[so] = hi; *(u32*)&sXil[so] = lo; \
    } }

    SCR_LOAD(0)
    SCR_STORE(0)
    __syncthreads();
    for (int it = 0; it < 8; it++) {
        int buf = it & 1;
        if (it < 7) SCR_LOAD((it + 1) * 32)
        u32 aGrh = smaddr(sGrh + buf * SSZ), aGrl = smaddr(sGrl + buf * SSZ);
        u32 aGih = smaddr(sGih + buf * SSZ), aGil = smaddr(sGil + buf * SSZ);
        u32 aXrh = smaddr(sXrh + buf * SSZ), aXrl = smaddr(sXrl + buf * SSZ);
        u32 aXih = smaddr(sXih + buf * SSZ), aXil = smaddr(sXil + buf * SSZ);
#pragma unroll
        for (int ks = 0; ks < 2; ks++) {
            int kb = ks * 16;
            u32 grh[2][4], grl[2][4], gih[2][4], gil[2][4];
#pragma unroll
            for (int tm = 0; tm < 2; tm++) {
                u32 off = ((kb + kA) * PITS + wm + 16 * tm + mA) * 2;
                ldmAT(grh[tm], aGrh + off);
                ldmAT(grl[tm], aGrl + off);
                ldmAT(gih[tm], aGih + off);
                ldmAT(gil[tm], aGil + off);
            }
            u32 xrh[2][2], xrl[2][2], xih[2][2], xil[2][2];
#pragma unroll
            for (int tn = 0; tn < 2; tn++) {
                u32 off = ((kb + kB) * PITS + wn + 8 * tn) * 2;
                ldmBT(xrh[tn], aXrh + off);
                ldmBT(xrl[tn], aXrl + off);
                ldmBT(xih[tn], aXih + off);
                ldmBT(xil[tn], aXil + off);
            }
#pragma unroll
            for (int tm = 0; tm < 2; tm++) {
                u32 nih[4], nil_[4];
#pragma unroll
                for (int q = 0; q < 4; q++) {
                    nih[q]  = gih[tm][q] ^ 0x80008000u;
                    nil_[q] = gil[tm][q] ^ 0x80008000u;
                }
#pragma unroll
                for (int tn = 0; tn < 2; tn++) {
                    mma_bf16(are[tm][tn], grh[tm], xrh[tn]);
                    mma_bf16(are[tm][tn], grh[tm], xrl[tn]);
                    mma_bf16(are[tm][tn], grl[tm], xrh[tn]);
                    mma_bf16(are[tm][tn], nih,     xih[tn]);
                    mma_bf16(are[tm][tn], nih,     xil[tn]);
                    mma_bf16(are[tm][tn], nil_,    xih[tn]);
                    mma_bf16(aim[tm][tn], grh[tm], xih[tn]);
                    mma_bf16(aim[tm][tn], grh[tm], xil[tn]);
                    mma_bf16(aim[tm][tn], grl[tm], xih[tn]);
                    mma_bf16(aim[tm][tn], gih[tm], xrh[tn]);
                    mma_bf16(aim[tm][tn], gih[tm], xrl[tn]);
                    mma_bf16(aim[tm][tn], gil[tm], xrh[tn]);
                }
            }
        }
        if (it < 7) SCR_STORE(buf ^ 1)
        __syncthreads();
    }
#undef SCR_LOAD
#undef SCR_STORE
#pragma unroll
    for (int tm = 0; tm < 2; tm++)
#pragma unroll
        for (int tn = 0; tn < 2; tn++) {
            int r0 = m0 + wm + 16 * tm + g;
            int col = n0 + wn + 8 * tn + 2 * tc4;
            float s0 = rsq[bc * Hh + r0], s1 = rsq[bc * Hh + r0 + 8];
            float4 o0 = make_float4(
                sigm(are[tm][tn][0] * s0), sigm(aim[tm][tn][0] * s0),
                sigm(are[tm][tn][1] * s0), sigm(aim[tm][tn][1] * s0));
            *(float4*)&Cp[(size_t)r0 * 256 + col] = o0;
            float4 o1 = make_float4(
                sigm(are[tm][tn][2] * s1), sigm(aim[tm][tn][2] * s1),
                sigm(are[tm][tn][3] * s1), sigm(aim[tm][tn][3] * s1));
            *(float4*)&Cp[(size_t)(r0 + 8) * 256 + col] = o1;
        }
}

// ------- channel LayerNorm — single-read smem-tiled -------
__global__ void __launch_bounds__(256) ln_kernel(
    const float* __restrict__ r, const float* __restrict__ gamma,
    const float* __restrict__ beta, float* __restrict__ out)
{
    __shared__ float tile[128][64];
    __shared__ float ps[4][64], qs[4][64];
    __shared__ float mu[64], inv[64];
    int blk = blockIdx.x;
    int b = blk / 2040;
    int w0 = (blk - b * 2040) * 64;
    int t = threadIdx.x;
    int wl = t & 63, cq = t >> 6;

#pragma unroll 8
    for (int c0 = 0; c0 < 128; c0 += 4) {
        int c = c0 + cq;
        tile[c][wl] = r[(size_t)(b * Cc + c) * HWD + w0 + wl];
    }
    __syncthreads();
    {
        float s = 0.f, q = 0.f;
#pragma unroll
        for (int c = 0; c < 32; c++) {
            float v = tile[cq * 32 + c][wl];
            s += v; q += v * v;
        }
        ps[cq][wl] = s; qs[cq][wl] = q;
    }
    __syncthreads();
    if (t < 64) {
        float s = ps[0][t] + ps[1][t] + ps[2][t] + ps[3][t];
        float q = qs[0][t] + qs[1][t] + qs[2][t] + qs[3][t];
        float m = s * (1.f / 128.f);
        mu[t] = m;
        inv[t] = rsqrtf(q * (1.f / 128.f) - m * m + 1e-6f);
    }
    __syncthreads();
#pragma unroll 8
    for (int c0 = 0; c0 < 128; c0 += 4) {
        int c = c0 + cq;
        out[(size_t)(b * Cc + c) * HWD + w0 + wl] =
            gamma[c] * (tile[c][wl] - mu[wl]) * inv[wl] + beta[c];
    }
}

// ---------------- launch ----------------
extern "C" void kernel_launch(void* const* d_in, const int* in_sizes, int n_in,
                              void* d_out, int out_size)
{
    (void)in_sizes; (void)n_in; (void)out_size;
    const float*  g     = (const float*)d_in[0];
    const float*  x     = (const float*)d_in[1];
    const float*  wg    = (const float*)d_in[2];
    const float*  bg    = (const float*)d_in[3];
    const float*  wx    = (const float*)d_in[4];
    const float*  bx    = (const float*)d_in[5];
    const float2* fg    = (const float2*)d_in[6];
    const float2* fx    = (const float2*)d_in[7];
    const float*  gamma = (const float*)d_in[8];
    const float*  beta  = (const float*)d_in[9];
    float* out = (float*)d_out;

    float *yg, *yx, *rb, *rsq;
    float2 *Fg, *Fx, *Gg, *Gx, *S, *T;
    cudaGetSymbolAddress((void**)&yg,  d_yg);
    cudaGetSymbolAddress((void**)&yx,  d_yx);
    cudaGetSymbolAddress((void**)&Fg,  d_Fg);
    cudaGetSymbolAddress((void**)&Fx,  d_Fx);
    cudaGetSymbolAddress((void**)&Gg,  d_Gg);
    cudaGetSymbolAddress((void**)&Gx,  d_Gx);
    cudaGetSymbolAddress((void**)&S,   d_Sb);
    cudaGetSymbolAddress((void**)&T,   d_Tb);
    cudaGetSymbolAddress((void**)&rb,  d_rb);
    cudaGetSymbolAddress((void**)&rsq, d_rsq);

    static int attr_done = 0;
    if (!attr_done) {
        cudaFuncSetAttribute(scores_tc, cudaFuncAttributeMaxDynamicSharedMemorySize,
                             16 * SSZ * 2);
        attr_done = 1;
    }

    dim3 blk(16, 16);

    build_tables_kernel<<<256, 256>>>();
    pack_w_kernel<<<16, 256>>>(wg, wx);

    conv_tc<<<dim3(HWD / 64, 2, Bb), 256>>>(g, 0, bg, yg);
    conv_tc<<<dim3(HWD / 64, 2, Bb), 256>>>(x, 1, bx, yx);

    rfftw_tc<<<dim3(4, 4, BCD), 256>>>(yg, Fg);
    rfftw_tc<<<dim3(4, 4, BCD), 256>>>(yx, Fx);

    ffth_kernel<0, 1><<<dim3(16, BCD), blk>>>(Fg, Gg, fg);
    ffth_kernel<0, 1><<<dim3(16, BCD), blk>>>(Fx, Gx, fx);

    var_kernel<<<BCD * Hh, 256>>>(Gg, rsq);

    scores_tc<<<dim3(4, 4, BCD), 256, 16 * SSZ * 2>>>(Gg, Gx, rsq, S);

    ffth_kernel<1, 0><<<dim3(16, BCD), blk>>>(S, T, nullptr);

    irfft_add_tc<<<dim3(8, 4, BCD), 256>>>(T, x, rb);

    ln_kernel<<<Bb * 2040, 256>>>(rb, gamma, beta, out);
}

// round 13
// speedup vs baseline: 1.0173x; 1.0173x over previous
#include <cuda_runtime.h>
#include <cuda_bf16.h>
#include <math.h>

#define Bb  2
#define Cc  128
#define Hh  256
#define Ww  510
#define WFD 256
#define HWD 130560   /* 256*510 */
#define BCD 256      /* Bb*Cc */

typedef unsigned int u32;
typedef unsigned long long u64;

__device__ __forceinline__ u64 pk2(float lo, float hi) {
    u64 r; asm("mov.b64 %0,{%1,%2};" : "=l"(r) : "f"(lo), "f"(hi)); return r;
}
__device__ __forceinline__ float2 up2(u64 v) {
    float2 r; asm("mov.b64 {%0,%1},%2;" : "=f"(r.x), "=f"(r.y) : "l"(v)); return r;
}
__device__ __forceinline__ u64 ffma2(u64 a, u64 b, u64 c) {
    u64 d; asm("fma.rn.f32x2 %0,%1,%2,%3;" : "=l"(d) : "l"(a), "l"(b), "l"(c)); return d;
}

// ---- tensor-core helpers -------------------------------------------------
__device__ __forceinline__ void mma_bf16(float* c, const u32* a, const u32* b) {
    asm("mma.sync.aligned.m16n8k16.row.col.f32.bf16.bf16.f32 "
        "{%0,%1,%2,%3},{%4,%5,%6,%7},{%8,%9},{%0,%1,%2,%3};"
        : "+f"(c[0]), "+f"(c[1]), "+f"(c[2]), "+f"(c[3])
        : "r"(a[0]), "r"(a[1]), "r"(a[2]), "r"(a[3]), "r"(b[0]), "r"(b[1]));
}
__device__ __forceinline__ void ldmA(u32* a, u32 addr) {
    asm volatile("ldmatrix.sync.aligned.m8n8.x4.shared.b16 {%0,%1,%2,%3},[%4];"
        : "=r"(a[0]), "=r"(a[1]), "=r"(a[2]), "=r"(a[3]) : "r"(addr));
}
__device__ __forceinline__ void ldmAT(u32* a, u32 addr) {
    asm volatile("ldmatrix.sync.aligned.m8n8.x4.trans.shared.b16 {%0,%1,%2,%3},[%4];"
        : "=r"(a[0]), "=r"(a[1]), "=r"(a[2]), "=r"(a[3]) : "r"(addr));
}
__device__ __forceinline__ void ldmB(u32* b, u32 addr) {
    asm volatile("ldmatrix.sync.aligned.m8n8.x2.shared.b16 {%0,%1},[%2];"
        : "=r"(b[0]), "=r"(b[1]) : "r"(addr));
}
__device__ __forceinline__ void ldmBT(u32* b, u32 addr) {
    asm volatile("ldmatrix.sync.aligned.m8n8.x2.trans.shared.b16 {%0,%1},[%2];"
        : "=r"(b[0]), "=r"(b[1]) : "r"(addr));
}
__device__ __forceinline__ u32 smaddr(const void* p) {
    return (u32)__cvta_generic_to_shared(p);
}
__device__ __forceinline__ void bsplit2(float a, float b, u32& hi, u32& lo) {
    __nv_bfloat16 ha = __float2bfloat16(a), hb = __float2bfloat16(b);
    hi = (u32)__bfloat16_as_ushort(ha) | ((u32)__bfloat16_as_ushort(hb) << 16);
    float ra = a - __bfloat162float(ha), rb = b - __bfloat162float(hb);
    __nv_bfloat16 la = __float2bfloat16(ra), lb = __float2bfloat16(rb);
    lo = (u32)__bfloat16_as_ushort(la) | ((u32)__bfloat16_as_ushort(lb) << 16);
}

// ---------------- scratch ----------------
__device__ float  d_yg [(size_t)BCD * HWD];
__device__ float  d_yx [(size_t)BCD * HWD];
__device__ float2 d_Fg [(size_t)BCD * Hh * WFD];
__device__ float2 d_Fx [(size_t)BCD * Hh * WFD];
__device__ float2 d_Gg [(size_t)BCD * Hh * WFD];
__device__ float2 d_Gx [(size_t)BCD * Hh * WFD];
__device__ float2 d_Sb [(size_t)BCD * WFD * WFD];
__device__ float2 d_Tb [(size_t)BCD * Hh * WFD];
__device__ float  d_rb [(size_t)BCD * HWD];
__device__ float  d_rsq[BCD * Hh];
__device__ float2 d_W256[256];
// mma-fragment-order DFT tables
__device__ u64 d_DwFrh[32768], d_DwFrl[32768], d_DwFih[32768], d_DwFil[32768];
__device__ u64 d_CwF1h[32768], d_CwF1l[32768], d_CwF2h[32768], d_CwF2l[32768];
// conv weight A-fragment tables: [wsel][{01h,01l,23h,23l}][ (mblk*8+kblk)*32+lane ]
__device__ u64 d_WF[2][4][2048];

__device__ __forceinline__ void sp_bits(float x, u32& hb, u32& lb) {
    __nv_bfloat16 h = __float2bfloat16(x);
    hb = (u32)__bfloat16_as_ushort(h);
    lb = (u32)__bfloat16_as_ushort(__float2bfloat16(x - __bfloat162float(h)));
}

// ---------------- table builder ----------------
__global__ void build_tables_kernel() {
    int idx = blockIdx.x * blockDim.x + threadIdx.x;
    int stride = gridDim.x * blockDim.x;
    float rsW = rsqrtf(510.0f);

    for (int i = idx; i < 32768; i += stride) {
        int lane = i & 31, kblk = (i >> 5) & 31, nblk = i >> 10;
        int v = nblk * 8 + (lane >> 2);
        u32 prh[2], prl[2], pih[2], pil[2];
#pragma unroll
        for (int reg = 0; reg < 2; reg++) {
            prh[reg] = prl[reg] = pih[reg] = pil[reg] = 0;
#pragma unroll
            for (int e = 0; e < 2; e++) {
                int w = kblk * 16 + (lane & 3) * 2 + e + reg * 8;
                float re = 0.f, im = 0.f;
                if (w < Ww) {
                    int m = (w * v) % Ww;
                    float s, c; sincospif(2.0f * (float)m / (float)Ww, &s, &c);
                    re = c * rsW; im = -s * rsW;
                }
                u32 hb, lb;
                sp_bits(re, hb, lb);
                prh[reg] |= hb << (16 * e); prl[reg] |= lb << (16 * e);
                sp_bits(im, hb, lb);
                pih[reg] |= hb << (16 * e); pil[reg] |= lb << (16 * e);
            }
        }
        d_DwFrh[i] = (u64)prh[0] | ((u64)prh[1] << 32);
        d_DwFrl[i] = (u64)prl[0] | ((u64)prl[1] << 32);
        d_DwFih[i] = (u64)pih[0] | ((u64)pih[1] << 32);
        d_DwFil[i] = (u64)pil[0] | ((u64)pil[1] << 32);
    }
    for (int i = idx; i < 32768; i += stride) {
        int lane = i & 31, kblk = (i >> 5) & 15, nblk = i >> 9;
        int w = nblk * 8 + (lane >> 2);
        u32 p1h[2], p1l[2], p2h[2], p2l[2];
#pragma unroll
        for (int reg = 0; reg < 2; reg++) {
            p1h[reg] = p1l[reg] = p2h[reg] = p2l[reg] = 0;
#pragma unroll
            for (int e = 0; e < 2; e++) {
                int v = kblk * 16 + (lane & 3) * 2 + e + reg * 8;
                float b1 = 0.f, b2 = 0.f;
                if (w < Ww) {
                    int m = (v * w) % Ww;
                    float s, c; sincospif(2.0f * (float)m / (float)Ww, &s, &c);
                    float sv = (v == 0 || v == 255) ? 1.0f : 2.0f;
                    b1 = sv * c * rsW; b2 = -sv * s * rsW;
                }
                u32 hb, lb;
                sp_bits(b1, hb, lb);
                p1h[reg] |= hb << (16 * e); p1l[reg] |= lb << (16 * e);
                sp_bits(b2, hb, lb);
                p2h[reg] |= hb << (16 * e); p2l[reg] |= lb << (16 * e);
            }
        }
        d_CwF1h[i] = (u64)p1h[0] | ((u64)p1h[1] << 32);
        d_CwF1l[i] = (u64)p1l[0] | ((u64)p1l[1] << 32);
        d_CwF2h[i] = (u64)p2h[0] | ((u64)p2h[1] << 32);
        d_CwF2l[i] = (u64)p2l[0] | ((u64)p2l[1] << 32);
    }
    for (int j = idx; j < 256; j += stride) {
        float s, c; sincospif(2.0f * (float)j / 256.0f, &s, &c);
        d_W256[j] = make_float2(c, -s);
    }
}

// ---------------- W pack: 128x128 -> A-fragment order (hi/lo) ----------------
__global__ void pack_w_kernel(const float* __restrict__ wg, const float* __restrict__ wx) {
    int t = blockIdx.x * blockDim.x + threadIdx.x;   // 0..4095
    if (t >= 4096) return;
    int wsel = t >> 11;
    int i = t & 2047;
    const float* W = wsel ? wx : wg;
    int lane = i & 31, kblk = (i >> 5) & 7, mblk = i >> 8;
    u32 qh[4], ql[4];
#pragma unroll
    for (int reg = 0; reg < 4; reg++) {
        int row = mblk * 16 + (lane >> 2) + 8 * (reg & 1);
        u32 hi = 0, lo = 0;
#pragma unroll
        for (int e = 0; e < 2; e++) {
            int k = kblk * 16 + (lane & 3) * 2 + e + 8 * (reg >> 1);
            float v = W[row * 128 + k];
            u32 hb, lb; sp_bits(v, hb, lb);
            hi |= hb << (16 * e); lo |= lb << (16 * e);
        }
        qh[reg] = hi; ql[reg] = lo;
    }
    d_WF[wsel][0][i] = (u64)qh[0] | ((u64)qh[1] << 32);
    d_WF[wsel][1][i] = (u64)ql[0] | ((u64)ql[1] << 32);
    d_WF[wsel][2][i] = (u64)qh[2] | ((u64)qh[3] << 32);
    d_WF[wsel][3][i] = (u64)ql[2] | ((u64)ql[3] << 32);
}

__device__ __forceinline__ float sigm(float v) { return 1.f / (1.f + expf(-v)); }

#define PIT  40
#define PITS 72
#define ASZ  (64 * PIT)
#define SSZ  (32 * PITS)

// ---------------- 1x1 conv — HMMA, W fragments direct from gmem ----------------
__global__ void __launch_bounds__(256, 2) conv_tc(
    const float* __restrict__ X, int wsel,
    const float* __restrict__ bias, float* __restrict__ Y)
{
    __shared__ __nv_bfloat16 sXh[2][SSZ], sXl[2][SSZ];
    int b = blockIdx.z;
    const float* Xb = X + (size_t)b * Cc * HWD;
    float* Yb = Y + (size_t)b * Cc * HWD;
    int n0 = blockIdx.x * 64, m0 = blockIdx.y * 64;
    int t = threadIdx.x, lane = t & 31, wid = t >> 5;
    int wm = (wid >> 2) * 32, wn = (wid & 3) * 16;
    int g = lane >> 2, tc4 = lane & 3;

    float acc[2][2][4];
#pragma unroll
    for (int i = 0; i < 2; i++)
#pragma unroll
        for (int j = 0; j < 2; j++)
#pragma unroll
            for (int q = 0; q < 4; q++) acc[i][j][q] = 0.f;

    int kB = (lane & 7) + ((lane >> 3) & 1) * 8;
    int scB = t & 31, srB = t >> 5;
    int mblk_base = (m0 + wm) >> 4;

    float2 xv[4];
#define CONV_LOAD(K0) { \
    _Pragma("unroll") \
    for (int i = 0; i < 4; i++) \
        xv[i] = *(const float2*)&Xb[(size_t)((K0) + srB + i * 8) * HWD + n0 + 2 * scB]; }
#define CONV_STORE(BF) { \
    _Pragma("unroll") \
    for (int i = 0; i < 4; i++) { \
        u32 hi, lo; bsplit2(xv[i].x, xv[i].y, hi, lo); \
        int so = (srB + i * 8) * PITS + 2 * scB; \
        *(u32*)&sXh[BF][so] = hi; *(u32*)&sXl[BF][so] = lo; \
    } }

    CONV_LOAD(0)
    CONV_STORE(0)
    __syncthreads();
    for (int it = 0; it < 4; it++) {
        int buf = it & 1;
        if (it < 3) CONV_LOAD((it + 1) * 32)
        u32 aXh = smaddr(sXh[buf]), aXl = smaddr(sXl[buf]);
#pragma unroll
        for (int ks = 0; ks < 2; ks++) {
            int kb = ks * 16;
            int kblk = it * 2 + ks;
            u32 ah[2][4], al[2][4];
#pragma unroll
            for (int tm = 0; tm < 2; tm++) {
                size_t bi = ((size_t)((mblk_base + tm) * 8 + kblk) << 5) + lane;
                u64 v;
                v = d_WF[wsel][0][bi]; ah[tm][0] = (u32)v; ah[tm][1] = (u32)(v >> 32);
                v = d_WF[wsel][2][bi]; ah[tm][2] = (u32)v; ah[tm][3] = (u32)(v >> 32);
                v = d_WF[wsel][1][bi]; al[tm][0] = (u32)v; al[tm][1] = (u32)(v >> 32);
                v = d_WF[wsel][3][bi]; al[tm][2] = (u32)v; al[tm][3] = (u32)(v >> 32);
            }
            u32 bh[2][2], bl[2][2];
#pragma unroll
            for (int tn = 0; tn < 2; tn++) {
                u32 off = ((kb + kB) * PITS + wn + 8 * tn) * 2;
                ldmBT(bh[tn], aXh + off);
                ldmBT(bl[tn], aXl + off);
            }
#pragma unroll
            for (int tm = 0; tm < 2; tm++)
#pragma unroll
                for (int tn = 0; tn < 2; tn++) {
                    mma_bf16(acc[tm][tn], ah[tm], bh[tn]);
                    mma_bf16(acc[tm][tn], ah[tm], bl[tn]);
                    mma_bf16(acc[tm][tn], al[tm], bh[tn]);
                }
        }
        if (it < 3) CONV_STORE(buf ^ 1)
        __syncthreads();
    }
#undef CONV_LOAD
#undef CONV_STORE
#pragma unroll
    for (int tm = 0; tm < 2; tm++)
#pragma unroll
        for (int tn = 0; tn < 2; tn++) {
            int r0 = m0 + wm + 16 * tm + g;
            int col = n0 + wn + 8 * tn + 2 * tc4;
            float bv0 = bias[r0], bv1 = bias[r0 + 8];
            *(float2*)&Yb[(size_t)r0 * HWD + col] =
                make_float2(acc[tm][tn][0] + bv0, acc[tm][tn][1] + bv0);
            *(float2*)&Yb[(size_t)(r0 + 8) * HWD + col] =
                make_float2(acc[tm][tn][2] + bv1, acc[tm][tn][3] + bv1);
        }
}

// ------- rfft along W — HMMA, A via smem, B direct fragment LDG (R9 form) -------
__global__ void __launch_bounds__(256, 2) rfftw_tc(
    const float* __restrict__ Y, float2* __restrict__ F)
{
    __shared__ __nv_bfloat16 sAh[2][ASZ], sAl[2][ASZ];
    int bc = blockIdx.z;
    const float* A = Y + (size_t)bc * HWD;
    float2* Cp = F + (size_t)bc * Hh * WFD;
    int n0 = blockIdx.x * 64, m0 = blockIdx.y * 64;
    int t = threadIdx.x, lane = t & 31, wid = t >> 5;
    int wm = (wid >> 2) * 32, wn = (wid & 3) * 16;
    int g = lane >> 2, tc = lane & 3;

    float cre[2][2][4], cim[2][2][4];
#pragma unroll
    for (int i = 0; i < 2; i++)
#pragma unroll
        for (int j = 0; j < 2; j++)
#pragma unroll
            for (int q = 0; q < 4; q++) { cre[i][j][q] = 0.f; cim[i][j][q] = 0.f; }

    int lrA = lane & 15, lkA = (lane >> 4) * 8;
    int sc = t & 15, sr = t >> 4;
    int nblk0 = (n0 + wn) >> 3;

    float a0[4], a1[4];
#define RFW_LOAD(K0) { \
    _Pragma("unroll") \
    for (int i = 0; i < 4; i++) { \
        int r = sr + i * 16; int w = (K0) + 2 * sc; \
        if (w < Ww) { float2 t2 = *(const float2*)&A[(size_t)(m0 + r) * Ww + w]; \
                      a0[i] = t2.x; a1[i] = t2.y; } \
        else { a0[i] = 0.f; a1[i] = 0.f; } \
    } }
#define RFW_STORE(BF) { \
    _Pragma("unroll") \
    for (int i = 0; i < 4; i++) { \
        int so = (sr + i * 16) * PIT + 2 * sc; \
        u32 hi, lo; bsplit2(a0[i], a1[i], hi, lo); \
        *(u32*)&sAh[BF][so] = hi; *(u32*)&sAl[BF][so] = lo; \
    } }

    RFW_LOAD(0)
    RFW_STORE(0)
    __syncthreads();
    for (int it = 0; it < 16; it++) {
        int buf = it & 1;
        if (it < 15) RFW_LOAD((it + 1) * 32)
        u32 aAh = smaddr(sAh[buf]), aAl = smaddr(sAl[buf]);
#pragma unroll
        for (int ks = 0; ks < 2; ks++) {
            int kb = ks * 16;
            int kblk = it * 2 + ks;
            u32 ah[2][4], al[2][4];
#pragma unroll
            for (int tm = 0; tm < 2; tm++) {
                u32 off = ((wm + 16 * tm + lrA) * PIT + kb + lkA) * 2;
                ldmA(ah[tm], aAh + off);
                ldmA(al[tm], aAl + off);
            }
            u32 brh[2][2], brl[2][2], bih[2][2], bil[2][2];
#pragma unroll
            for (int tn = 0; tn < 2; tn++) {
                size_t bi = ((size_t)((nblk0 + tn) * 32 + kblk) << 5) + lane;
                u64 v;
                v = d_DwFrh[bi]; brh[tn][0] = (u32)v; brh[tn][1] = (u32)(v >> 32);
                v = d_DwFrl[bi]; brl[tn][0] = (u32)v; brl[tn][1] = (u32)(v >> 32);
                v = d_DwFih[bi]; bih[tn][0] = (u32)v; bih[tn][1] = (u32)(v >> 32);
                v = d_DwFil[bi]; bil[tn][0] = (u32)v; bil[tn][1] = (u32)(v >> 32);
            }
#pragma unroll
            for (int tm = 0; tm < 2; tm++)
#pragma unroll
                for (int tn = 0; tn < 2; tn++) {
                    mma_bf16(cre[tm][tn], ah[tm], brh[tn]);
                    mma_bf16(cre[tm][tn], ah[tm], brl[tn]);
                    mma_bf16(cre[tm][tn], al[tm], brh[tn]);
                    mma_bf16(cim[tm][tn], ah[tm], bih[tn]);
                    mma_bf16(cim[tm][tn], ah[tm], bil[tn]);
                    mma_bf16(cim[tm][tn], al[tm], bih[tn]);
                }
        }
        if (it < 15) RFW_STORE(buf ^ 1)
        __syncthreads();
    }
#undef RFW_LOAD
#undef RFW_STORE
#pragma unroll
    for (int tm = 0; tm < 2; tm++)
#pragma unroll
        for (int tn = 0; tn < 2; tn++) {
            int r0 = m0 + wm + 16 * tm + g;
            int col = n0 + wn + 8 * tn + 2 * tc;
            float4 v0 = make_float4(cre[tm][tn][0], cim[tm][tn][0], cre[tm][tn][1], cim[tm][tn][1]);
            *(float4*)&Cp[(size_t)r0 * WFD + col] = v0;
            float4 v1 = make_float4(cre[tm][tn][2], cim[tm][tn][2], cre[tm][tn][3], cim[tm][tn][3]);
            *(float4*)&Cp[(size_t)(r0 + 8) * WFD + col] = v1;
        }
}

// ------- irfft along W + residual — HMMA, A via smem, B direct fragment LDG ----
__global__ void __launch_bounds__(256, 2) irfft_add_tc(
    const float2* __restrict__ T, const float* __restrict__ x, float* __restrict__ r)
{
    __shared__ __nv_bfloat16 sArh[2][ASZ], sArl[2][ASZ], sAih[2][ASZ], sAil[2][ASZ];
    int bc = blockIdx.z;
    const float2* Ap = T + (size_t)bc * 65536;
    int n0 = blockIdx.x * 64, m0 = blockIdx.y * 64;
    int t = threadIdx.x, lane = t & 31, wid = t >> 5;
    int wm = (wid >> 2) * 32, wn = (wid & 3) * 16;
    int g = lane >> 2, tc = lane & 3;

    float acc[2][2][4];
#pragma unroll
    for (int i = 0; i < 2; i++)
#pragma unroll
        for (int j = 0; j < 2; j++)
#pragma unroll
            for (int q = 0; q < 4; q++) acc[i][j][q] = 0.f;

    int lrA = lane & 15, lkA = (lane >> 4) * 8;
    int sc = t & 15, sr = t >> 4;
    int nblk0 = (n0 + wn) >> 3;

    float4 va[4];
#define IRF_LOAD(K0) { \
    _Pragma("unroll") \
    for (int i = 0; i < 4; i++) { \
        int rr = sr + i * 16; \
        va[i] = *(const float4*)&Ap[(size_t)(m0 + rr) * 256 + (K0) + 2 * sc]; \
    } }
#define IRF_STORE(BF) { \
    _Pragma("unroll") \
    for (int i = 0; i < 4; i++) { \
        int so = (sr + i * 16) * PIT + 2 * sc; \
        u32 hi, lo; \
        bsplit2(va[i].x, va[i].z, hi, lo); \
        *(u32*)&sArh[BF][so] = hi; *(u32*)&sArl[BF][so] = lo; \
        bsplit2(va[i].y, va[i].w, hi, lo); \
        *(u32*)&sAih[BF][so] = hi; *(u32*)&sAil[BF][so] = lo; \
    } }

    IRF_LOAD(0)
    IRF_STORE(0)
    __syncthreads();
    for (int it = 0; it < 8; it++) {
        int buf = it & 1;
        if (it < 7) IRF_LOAD((it + 1) * 32)
        u32 aArh = smaddr(sArh[buf]), aArl = smaddr(sArl[buf]);
        u32 aAih = smaddr(sAih[buf]), aAil = smaddr(sAil[buf]);
#pragma unroll
        for (int ks = 0; ks < 2; ks++) {
            int kb = ks * 16;
            int kblk = it * 2 + ks;
            u32 arh[2][4], arl[2][4], aih[2][4], ail[2][4];
#pragma unroll
            for (int tm = 0; tm < 2; tm++) {
                u32 off = ((wm + 16 * tm + lrA) * PIT + kb + lkA) * 2;
                ldmA(arh[tm], aArh + off);
                ldmA(arl[tm], aArl + off);
                ldmA(aih[tm], aAih + off);
                ldmA(ail[tm], aAil + off);
            }
            u32 b1h[2][2], b1l[2][2], b2h[2][2], b2l[2][2];
#pragma unroll
            for (int tn = 0; tn < 2; tn++) {
                size_t bi = ((size_t)((nblk0 + tn) * 16 + kblk) << 5) + lane;
                u64 v;
                v = d_CwF1h[bi]; b1h[tn][0] = (u32)v; b1h[tn][1] = (u32)(v >> 32);
                v = d_CwF1l[bi]; b1l[tn][0] = (u32)v; b1l[tn][1] = (u32)(v >> 32);
                v = d_CwF2h[bi]; b2h[tn][0] = (u32)v; b2h[tn][1] = (u32)(v >> 32);
                v = d_CwF2l[bi]; b2l[tn][0] = (u32)v; b2l[tn][1] = (u32)(v >> 32);
            }
#pragma unroll
            for (int tm = 0; tm < 2; tm++)
#pragma unroll
                for (int tn = 0; tn < 2; tn++) {
                    mma_bf16(acc[tm][tn], arh[tm], b1h[tn]);
                    mma_bf16(acc[tm][tn], arh[tm], b1l[tn]);
                    mma_bf16(acc[tm][tn], arl[tm], b1h[tn]);
                    mma_bf16(acc[tm][tn], aih[tm], b2h[tn]);
                    mma_bf16(acc[tm][tn], aih[tm], b2l[tn]);
                    mma_bf16(acc[tm][tn], ail[tm], b2h[tn]);
                }
        }
        if (it < 7) IRF_STORE(buf ^ 1)
        __syncthreads();
    }
#undef IRF_LOAD
#undef IRF_STORE
#pragma unroll
    for (int tm = 0; tm < 2; tm++)
#pragma unroll
        for (int tn = 0; tn < 2; tn++) {
            int col = n0 + wn + 8 * tn + 2 * tc;
            if (col < Ww) {
                int r0 = m0 + wm + 16 * tm + g;
                size_t i0 = (size_t)bc * HWD + (size_t)r0 * Ww + col;
                size_t i1 = i0 + (size_t)8 * Ww;
                float2 xv = *(const float2*)&x[i0];
                *(float2*)&r[i0] = make_float2(acc[tm][tn][0] + xv.x, acc[tm][tn][1] + xv.y);
                xv = *(const float2*)&x[i1];
                *(float2*)&r[i1] = make_float2(acc[tm][tn][2] + xv.x, acc[tm][tn][3] + xv.y);
            }
        }
}

// ---------------- 256-pt FFT along slow axis (4-step 16x16) ----------------
template<int INV, int FILT>
__global__ void __launch_bounds__(256) ffth_kernel(
    const float2* __restrict__ in, float2* __restrict__ out,
    const float2* __restrict__ filt)
{
    __shared__ float2 Xs[256][17];
    __shared__ float2 Ws[256];
    int bc = blockIdx.y;
    int v0 = blockIdx.x * 16;
    int tx = threadIdx.x;
    int ty = threadIdx.y;
    int t = ty * 16 + tx;
    const float2* inp = in + (size_t)bc * 65536 + v0;
    float2* outp = out + (size_t)bc * 65536 + v0;

    {
        float2 w = d_W256[t];
        if (INV) w.y = -w.y;
        Ws[t] = w;
    }
#pragma unroll
    for (int i = 0; i < 16; i++) {
        int h = i * 16 + ty;
        Xs[h][tx] = inp[(size_t)h * 256 + tx];
    }
    __syncthreads();

    float2 rr[16];
    {
        u64 tw[16];
#pragma unroll
        for (int n1 = 0; n1 < 16; n1++) {
            float2 w = Ws[(n1 * ty * 16) & 255];
            tw[n1] = pk2(w.x, w.y);
        }
#pragma unroll
        for (int n2 = 0; n2 < 16; n2++) {
            u64 accA = 0ull, accB = 0ull;
#pragma unroll
            for (int n1 = 0; n1 < 16; n1++) {
                float2 xv = Xs[16 * n1 + n2][tx];
                u64 xp = pk2(xv.x, xv.y);
                u64 xq = pk2(xv.y, xv.x);
                accA = ffma2(xp, tw[n1], accA);
                accB = ffma2(xq, tw[n1], accB);
            }
            float2 a = up2(accA), b = up2(accB);
            float ar = a.x - a.y, ai = b.x + b.y;
            float2 tm = Ws[(n2 * ty) & 255];
            rr[n2] = make_float2(ar * tm.x - ai * tm.y, ar * tm.y + ai * tm.x);
        }
    }
    __syncthreads();
#pragma unroll
    for (int n2 = 0; n2 < 16; n2++)
        Xs[ty * 16 + n2][tx] = rr[n2];
    __syncthreads();

    {
        u64 tw[16];
#pragma unroll
        for (int n2 = 0; n2 < 16; n2++) {
            float2 w = Ws[(n2 * ty * 16) & 255];
            tw[n2] = pk2(w.x, w.y);
        }
        int c = bc & (Cc - 1);
#pragma unroll
        for (int k1 = 0; k1 < 16; k1++) {
            u64 accA = 0ull, accB = 0ull;
#pragma unroll
            for (int n2 = 0; n2 < 16; n2++) {
                float2 xv = Xs[k1 * 16 + n2][tx];
                u64 xp = pk2(xv.x, xv.y);
                u64 xq = pk2(xv.y, xv.x);
                accA = ffma2(xp, tw[n2], accA);
                accB = ffma2(xq, tw[n2], accB);
            }
            float2 a = up2(accA), b = up2(accB);
            int u = k1 + 16 * ty;
            float2 v = make_float2((a.x - a.y) * 0.0625f, (b.x + b.y) * 0.0625f);
            if (FILT) {
                float2 wc = filt[((size_t)c * Hh + u) * WFD + v0 + tx];
                v = make_float2(v.x * wc.x - v.y * wc.y, v.x * wc.y + v.y * wc.x);
            }
            outp[(size_t)u * 256 + tx] = v;
        }
    }
}

// ------- variance over v per (bc,u) row -------
__global__ void var_kernel(const float2* __restrict__ G, float* __restrict__ rsq)
{
    __shared__ float s0[256], s1[256], s2[256];
    int row = blockIdx.x;
    int tid = threadIdx.x;
    float2 z = G[(size_t)row * WFD + tid];
    s0[tid] = z.x; s1[tid] = z.y; s2[tid] = z.x * z.x + z.y * z.y;
    __syncthreads();
    for (int s = 128; s > 0; s >>= 1) {
        if (tid < s) { s0[tid] += s0[tid + s]; s1[tid] += s1[tid + s]; s2[tid] += s2[tid + s]; }
        __syncthreads();
    }
    if (tid == 0) {
        float mr = s0[0] * (1.f / WFD), mi = s1[0] * (1.f / WFD);
        float var = s2[0] * (1.f / WFD) - (mr * mr + mi * mi);
        rsq[row] = 1.f / sqrtf(6.283185307179586f * var);
    }
}

// ------- scores — HMMA complex, double-buffered (dynamic smem) -------
__global__ void __launch_bounds__(256) scores_tc(
    const float2* __restrict__ Gb, const float2* __restrict__ Xb,
    const float* __restrict__ rsq, float2* __restrict__ Sb)
{
    extern __shared__ __nv_bfloat16 dynS[];
    __nv_bfloat16* sGrh = dynS;
    __nv_bfloat16* sGrl = sGrh + 2 * SSZ;
    __nv_bfloat16* sGih = sGrl + 2 * SSZ;
    __nv_bfloat16* sGil = sGih + 2 * SSZ;
    __nv_bfloat16* sXrh = sGil + 2 * SSZ;
    __nv_bfloat16* sXrl = sXrh + 2 * SSZ;
    __nv_bfloat16* sXih = sXrl + 2 * SSZ;
    __nv_bfloat16* sXil = sXih + 2 * SSZ;
    int bc = blockIdx.z;
    const float2* Ap = Gb + (size_t)bc * 65536;
    const float2* Bp = Xb + (size_t)bc * 65536;
    float2* Cp = Sb + (size_t)bc * 65536;
    int n0 = blockIdx.x * 64, m0 = blockIdx.y * 64;
    int t = threadIdx.x, lane = t & 31, wid = t >> 5;
    int wm = (wid >> 2) * 32, wn = (wid & 3) * 16;
    int g = lane >> 2, tc4 = lane & 3;

    float are[2][2][4], aim[2][2][4];
#pragma unroll
    for (int i = 0; i < 2; i++)
#pragma unroll
        for (int j = 0; j < 2; j++)
#pragma unroll
            for (int q = 0; q < 4; q++) { are[i][j][q] = 0.f; aim[i][j][q] = 0.f; }

    int kA = (lane & 7) + ((lane >> 4) & 1) * 8;
    int mA = ((lane >> 3) & 1) * 8;
    int kB = (lane & 7) + ((lane >> 3) & 1) * 8;
    int sc = t & 31, sr = t >> 5;

    float4 vA[4], vB[4];
#define SCR_LOAD(K0) { \
    _Pragma("unroll") \
    for (int i = 0; i < 4; i++) { \
        int k = sr + i * 8; \
        vA[i] = *(const float4*)&Ap[(size_t)((K0) + k) * 256 + m0 + 2 * sc]; \
        vB[i] = *(const float4*)&Bp[(size_t)((K0) + k) * 256 + n0 + 2 * sc]; \
    } }
#define SCR_STORE(BF) { \
    _Pragma("unroll") \
    for (int i = 0; i < 4; i++) { \
        int so = (BF) * SSZ + (sr + i * 8) * PITS + 2 * sc; \
        u32 hi, lo; \
        bsplit2(vA[i].x, vA[i].z, hi, lo); *(u32*)&sGrh[so] = hi; *(u32*)&sGrl[so] = lo; \
        bsplit2(vA[i].y, vA[i].w, hi, lo); *(u32*)&sGih[so] = hi; *(u32*)&sGil[so] = lo; \
        bsplit2(vB[i].x, vB[i].z, hi, lo); *(u32*)&sXrh[so] = hi; *(u32*)&sXrl[so] = lo; \
        bsplit2(vB[i].y, vB[i].w, hi, lo); *(u32*)&sXih[so] = hi; *(u32*)&sXil[so] = lo; \
    } }

    SCR_LOAD(0)
    SCR_STORE(0)
    __syncthreads();
    for (int it = 0; it < 8; it++) {
        int buf = it & 1;
        if (it < 7) SCR_LOAD((it + 1) * 32)
        u32 aGrh = smaddr(sGrh + buf * SSZ), aGrl = smaddr(sGrl + buf * SSZ);
        u32 aGih = smaddr(sGih + buf * SSZ), aGil = smaddr(sGil + buf * SSZ);
        u32 aXrh = smaddr(sXrh + buf * SSZ), aXrl = smaddr(sXrl + buf * SSZ);
        u32 aXih = smaddr(sXih + buf * SSZ), aXil = smaddr(sXil + buf * SSZ);
#pragma unroll
        for (int ks = 0; ks < 2; ks++) {
            int kb = ks * 16;
            u32 grh[2][4], grl[2][4], gih[2][4], gil[2][4];
#pragma unroll
            for (int tm = 0; tm < 2; tm++) {
                u32 off = ((kb + kA) * PITS + wm + 16 * tm + mA) * 2;
                ldmAT(grh[tm], aGrh + off);
                ldmAT(grl[tm], aGrl + off);
                ldmAT(gih[tm], aGih + off);
                ldmAT(gil[tm], aGil + off);
            }
            u32 xrh[2][2], xrl[2][2], xih[2][2], xil[2][2];
#pragma unroll
            for (int tn = 0; tn < 2; tn++) {
                u32 off = ((kb + kB) * PITS + wn + 8 * tn) * 2;
                ldmBT(xrh[tn], aXrh + off);
                ldmBT(xrl[tn], aXrl + off);
                ldmBT(xih[tn], aXih + off);
                ldmBT(xil[tn], aXil + off);
            }
#pragma unroll
            for (int tm = 0; tm < 2; tm++) {
                u32 nih[4], nil_[4];
#pragma unroll
                for (int q = 0; q < 4; q++) {
                    nih[q]  = gih[tm][q] ^ 0x80008000u;
                    nil_[q] = gil[tm][q] ^ 0x80008000u;
                }
#pragma unroll
                for (int tn = 0; tn < 2; tn++) {
                    mma_bf16(are[tm][tn], grh[tm], xrh[tn]);
                    mma_bf16(are[tm][tn], grh[tm], xrl[tn]);
                    mma_bf16(are[tm][tn], grl[tm], xrh[tn]);
                    mma_bf16(are[tm][tn], nih,     xih[tn]);
                    mma_bf16(are[tm][tn], nih,     xil[tn]);
                    mma_bf16(are[tm][tn], nil_,    xih[tn]);
                    mma_bf16(aim[tm][tn], grh[tm], xih[tn]);
                    mma_bf16(aim[tm][tn], grh[tm], xil[tn]);
                    mma_bf16(aim[tm][tn], grl[tm], xih[tn]);
                    mma_bf16(aim[tm][tn], gih[tm], xrh[tn]);
                    mma_bf16(aim[tm][tn], gih[tm], xrl[tn]);
                    mma_bf16(aim[tm][tn], gil[tm], xrh[tn]);
                }
            }
        }
        if (it < 7) SCR_STORE(buf ^ 1)
        __syncthreads();
    }
#undef SCR_LOAD
#undef SCR_STORE
#pragma unroll
    for (int tm = 0; tm < 2; tm++)
#pragma unroll
        for (int tn = 0; tn < 2; tn++) {
            int r0 = m0 + wm + 16 * tm + g;
            int col = n0 + wn + 8 * tn + 2 * tc4;
            float s0 = rsq[bc * Hh + r0], s1 = rsq[bc * Hh + r0 + 8];
            float4 o0 = make_float4(
                sigm(are[tm][tn][0] * s0), sigm(aim[tm][tn][0] * s0),
                sigm(are[tm][tn][1] * s0), sigm(aim[tm][tn][1] * s0));
            *(float4*)&Cp[(size_t)r0 * 256 + col] = o0;
            float4 o1 = make_float4(
                sigm(are[tm][tn][2] * s1), sigm(aim[tm][tn][2] * s1),
                sigm(are[tm][tn][3] * s1), sigm(aim[tm][tn][3] * s1));
            *(float4*)&Cp[(size_t)(r0 + 8) * 256 + col] = o1;
        }
}

// ------- channel LayerNorm — single-read smem-tiled -------
__global__ void __launch_bounds__(256) ln_kernel(
    const float* __restrict__ r, const float* __restrict__ gamma,
    const float* __restrict__ beta, float* __restrict__ out)
{
    __shared__ float tile[128][64];
    __shared__ float ps[4][64], qs[4][64];
    __shared__ float mu[64], inv[64];
    int blk = blockIdx.x;
    int b = blk / 2040;
    int w0 = (blk - b * 2040) * 64;
    int t = threadIdx.x;
    int wl = t & 63, cq = t >> 6;

#pragma unroll 8
    for (int c0 = 0; c0 < 128; c0 += 4) {
        int c = c0 + cq;
        tile[c][wl] = r[(size_t)(b * Cc + c) * HWD + w0 + wl];
    }
    __syncthreads();
    {
        float s = 0.f, q = 0.f;
#pragma unroll
        for (int c = 0; c < 32; c++) {
            float v = tile[cq * 32 + c][wl];
            s += v; q += v * v;
        }
        ps[cq][wl] = s; qs[cq][wl] = q;
    }
    __syncthreads();
    if (t < 64) {
        float s = ps[0][t] + ps[1][t] + ps[2][t] + ps[3][t];
        float q = qs[0][t] + qs[1][t] + qs[2][t] + qs[3][t];
        float m = s * (1.f / 128.f);
        mu[t] = m;
        inv[t] = rsqrtf(q * (1.f / 128.f) - m * m + 1e-6f);
    }
    __syncthreads();
#pragma unroll 8
    for (int c0 = 0; c0 < 128; c0 += 4) {
        int c = c0 + cq;
        out[(size_t)(b * Cc + c) * HWD + w0 + wl] =
            gamma[c] * (tile[c][wl] - mu[wl]) * inv[wl] + beta[c];
    }
}

// ---------------- launch ----------------
extern "C" void kernel_launch(void* const* d_in, const int* in_sizes, int n_in,
                              void* d_out, int out_size)
{
    (void)in_sizes; (void)n_in; (void)out_size;
    const float*  g     = (const float*)d_in[0];
    const float*  x     = (const float*)d_in[1];
    const float*  wg    = (const float*)d_in[2];
    const float*  bg    = (const float*)d_in[3];
    const float*  wx    = (const float*)d_in[4];
    const float*  bx    = (const float*)d_in[5];
    const float2* fg    = (const float2*)d_in[6];
    const float2* fx    = (const float2*)d_in[7];
    const float*  gamma = (const float*)d_in[8];
    const float*  beta  = (const float*)d_in[9];
    float* out = (float*)d_out;

    float *yg, *yx, *rb, *rsq;
    float2 *Fg, *Fx, *Gg, *Gx, *S, *T;
    cudaGetSymbolAddress((void**)&yg,  d_yg);
    cudaGetSymbolAddress((void**)&yx,  d_yx);
    cudaGetSymbolAddress((void**)&Fg,  d_Fg);
    cudaGetSymbolAddress((void**)&Fx,  d_Fx);
    cudaGetSymbolAddress((void**)&Gg,  d_Gg);
    cudaGetSymbolAddress((void**)&Gx,  d_Gx);
    cudaGetSymbolAddress((void**)&S,   d_Sb);
    cudaGetSymbolAddress((void**)&T,   d_Tb);
    cudaGetSymbolAddress((void**)&rb,  d_rb);
    cudaGetSymbolAddress((void**)&rsq, d_rsq);

    static int attr_done = 0;
    if (!attr_done) {
        cudaFuncSetAttribute(scores_tc, cudaFuncAttributeMaxDynamicSharedMemorySize,
                             16 * SSZ * 2);
        attr_done = 1;
    }

    dim3 blk(16, 16);

    build_tables_kernel<<<256, 256>>>();
    pack_w_kernel<<<16, 256>>>(wg, wx);

    conv_tc<<<dim3(HWD / 64, 2, Bb), 256>>>(g, 0, bg, yg);
    conv_tc<<<dim3(HWD / 64, 2, Bb), 256>>>(x, 1, bx, yx);

    rfftw_tc<<<dim3(4, 4, BCD), 256>>>(yg, Fg);
    rfftw_tc<<<dim3(4, 4, BCD), 256>>>(yx, Fx);

    ffth_kernel<0, 1><<<dim3(16, BCD), blk>>>(Fg, Gg, fg);
    ffth_kernel<0, 1><<<dim3(16, BCD), blk>>>(Fx, Gx, fx);

    var_kernel<<<BCD * Hh, 256>>>(Gg, rsq);

    scores_tc<<<dim3(4, 4, BCD), 256, 16 * SSZ * 2>>>(Gg, Gx, rsq, S);

    ffth_kernel<1, 0><<<dim3(16, BCD), blk>>>(S, T, nullptr);

    irfft_add_tc<<<dim3(8, 4, BCD), 256>>>(T, x, rb);

    ln_kernel<<<Bb * 2040, 256>>>(rb, gamma, beta, out);
}

// round 14
// speedup vs baseline: 1.0531x; 1.0352x over previous
#include <cuda_runtime.h>
#include <cuda_bf16.h>
#include <math.h>

#define Bb  2
#define Cc  128
#define Hh  256
#define Ww  510
#define WFD 256
#define HWD 130560   /* 256*510 */
#define BCD 256      /* Bb*Cc */

typedef unsigned int u32;
typedef unsigned long long u64;

__device__ __forceinline__ u64 pk2(float lo, float hi) {
    u64 r; asm("mov.b64 %0,{%1,%2};" : "=l"(r) : "f"(lo), "f"(hi)); return r;
}
__device__ __forceinline__ float2 up2(u64 v) {
    float2 r; asm("mov.b64 {%0,%1},%2;" : "=f"(r.x), "=f"(r.y) : "l"(v)); return r;
}
__device__ __forceinline__ u64 ffma2(u64 a, u64 b, u64 c) {
    u64 d; asm("fma.rn.f32x2 %0,%1,%2,%3;" : "=l"(d) : "l"(a), "l"(b), "l"(c)); return d;
}

// ---- tensor-core helpers -------------------------------------------------
__device__ __forceinline__ void mma_bf16(float* c, const u32* a, const u32* b) {
    asm("mma.sync.aligned.m16n8k16.row.col.f32.bf16.bf16.f32 "
        "{%0,%1,%2,%3},{%4,%5,%6,%7},{%8,%9},{%0,%1,%2,%3};"
        : "+f"(c[0]), "+f"(c[1]), "+f"(c[2]), "+f"(c[3])
        : "r"(a[0]), "r"(a[1]), "r"(a[2]), "r"(a[3]), "r"(b[0]), "r"(b[1]));
}
__device__ __forceinline__ void ldmA(u32* a, u32 addr) {
    asm volatile("ldmatrix.sync.aligned.m8n8.x4.shared.b16 {%0,%1,%2,%3},[%4];"
        : "=r"(a[0]), "=r"(a[1]), "=r"(a[2]), "=r"(a[3]) : "r"(addr));
}
__device__ __forceinline__ void ldmAT(u32* a, u32 addr) {
    asm volatile("ldmatrix.sync.aligned.m8n8.x4.trans.shared.b16 {%0,%1,%2,%3},[%4];"
        : "=r"(a[0]), "=r"(a[1]), "=r"(a[2]), "=r"(a[3]) : "r"(addr));
}
__device__ __forceinline__ void ldmB(u32* b, u32 addr) {
    asm volatile("ldmatrix.sync.aligned.m8n8.x2.shared.b16 {%0,%1},[%2];"
        : "=r"(b[0]), "=r"(b[1]) : "r"(addr));
}
__device__ __forceinline__ void ldmBT(u32* b, u32 addr) {
    asm volatile("ldmatrix.sync.aligned.m8n8.x2.trans.shared.b16 {%0,%1},[%2];"
        : "=r"(b[0]), "=r"(b[1]) : "r"(addr));
}
__device__ __forceinline__ u32 smaddr(const void* p) {
    return (u32)__cvta_generic_to_shared(p);
}
__device__ __forceinline__ void bsplit2(float a, float b, u32& hi, u32& lo) {
    __nv_bfloat16 ha = __float2bfloat16(a), hb = __float2bfloat16(b);
    hi = (u32)__bfloat16_as_ushort(ha) | ((u32)__bfloat16_as_ushort(hb) << 16);
    float ra = a - __bfloat162float(ha), rb = b - __bfloat162float(hb);
    __nv_bfloat16 la = __float2bfloat16(ra), lb = __float2bfloat16(rb);
    lo = (u32)__bfloat16_as_ushort(la) | ((u32)__bfloat16_as_ushort(lb) << 16);
}

// ---------------- scratch ----------------
__device__ float  d_yg [(size_t)BCD * HWD];
__device__ float  d_yx [(size_t)BCD * HWD];
__device__ float2 d_Fg [(size_t)BCD * Hh * WFD];
__device__ float2 d_Fx [(size_t)BCD * Hh * WFD];
__device__ float2 d_Gg [(size_t)BCD * Hh * WFD];
__device__ float2 d_Gx [(size_t)BCD * Hh * WFD];
__device__ float2 d_Sb [(size_t)BCD * WFD * WFD];
__device__ float2 d_Tb [(size_t)BCD * Hh * WFD];
__device__ float  d_rb [(size_t)BCD * HWD];
__device__ float  d_rsq[BCD * Hh];
__device__ float  d_vp [(size_t)BCD * Hh * 64];   // [bc][u][16 blk][4]
__device__ float2 d_W256[256];
// mma-fragment-order DFT tables
__device__ u64 d_DwFrh[32768], d_DwFrl[32768], d_DwFih[32768], d_DwFil[32768];
__device__ u64 d_CwF1h[32768], d_CwF1l[32768], d_CwF2h[32768], d_CwF2l[32768];
// conv weight A-fragment tables
__device__ u64 d_WF[2][4][2048];

__device__ __forceinline__ void sp_bits(float x, u32& hb, u32& lb) {
    __nv_bfloat16 h = __float2bfloat16(x);
    hb = (u32)__bfloat16_as_ushort(h);
    lb = (u32)__bfloat16_as_ushort(__float2bfloat16(x - __bfloat162float(h)));
}

// ---------------- table builder ----------------
__global__ void build_tables_kernel() {
    int idx = blockIdx.x * blockDim.x + threadIdx.x;
    int stride = gridDim.x * blockDim.x;
    float rsW = rsqrtf(510.0f);

    for (int i = idx; i < 32768; i += stride) {
        int lane = i & 31, kblk = (i >> 5) & 31, nblk = i >> 10;
        int v = nblk * 8 + (lane >> 2);
        u32 prh[2], prl[2], pih[2], pil[2];
#pragma unroll
        for (int reg = 0; reg < 2; reg++) {
            prh[reg] = prl[reg] = pih[reg] = pil[reg] = 0;
#pragma unroll
            for (int e = 0; e < 2; e++) {
                int w = kblk * 16 + (lane & 3) * 2 + e + reg * 8;
                float re = 0.f, im = 0.f;
                if (w < Ww) {
                    int m = (w * v) % Ww;
                    float s, c; sincospif(2.0f * (float)m / (float)Ww, &s, &c);
                    re = c * rsW; im = -s * rsW;
                }
                u32 hb, lb;
                sp_bits(re, hb, lb);
                prh[reg] |= hb << (16 * e); prl[reg] |= lb << (16 * e);
                sp_bits(im, hb, lb);
                pih[reg] |= hb << (16 * e); pil[reg] |= lb << (16 * e);
            }
        }
        d_DwFrh[i] = (u64)prh[0] | ((u64)prh[1] << 32);
        d_DwFrl[i] = (u64)prl[0] | ((u64)prl[1] << 32);
        d_DwFih[i] = (u64)pih[0] | ((u64)pih[1] << 32);
        d_DwFil[i] = (u64)pil[0] | ((u64)pil[1] << 32);
    }
    for (int i = idx; i < 32768; i += stride) {
        int lane = i & 31, kblk = (i >> 5) & 15, nblk = i >> 9;
        int w = nblk * 8 + (lane >> 2);
        u32 p1h[2], p1l[2], p2h[2], p2l[2];
#pragma unroll
        for (int reg = 0; reg < 2; reg++) {
            p1h[reg] = p1l[reg] = p2h[reg] = p2l[reg] = 0;
#pragma unroll
            for (int e = 0; e < 2; e++) {
                int v = kblk * 16 + (lane & 3) * 2 + e + reg * 8;
                float b1 = 0.f, b2 = 0.f;
                if (w < Ww) {
                    int m = (v * w) % Ww;
                    float s, c; sincospif(2.0f * (float)m / (float)Ww, &s, &c);
                    float sv = (v == 0 || v == 255) ? 1.0f : 2.0f;
                    b1 = sv * c * rsW; b2 = -sv * s * rsW;
                }
                u32 hb, lb;
                sp_bits(b1, hb, lb);
                p1h[reg] |= hb << (16 * e); p1l[reg] |= lb << (16 * e);
                sp_bits(b2, hb, lb);
                p2h[reg] |= hb << (16 * e); p2l[reg] |= lb << (16 * e);
            }
        }
        d_CwF1h[i] = (u64)p1h[0] | ((u64)p1h[1] << 32);
        d_CwF1l[i] = (u64)p1l[0] | ((u64)p1l[1] << 32);
        d_CwF2h[i] = (u64)p2h[0] | ((u64)p2h[1] << 32);
        d_CwF2l[i] = (u64)p2l[0] | ((u64)p2l[1] << 32);
    }
    for (int j = idx; j < 256; j += stride) {
        float s, c; sincospif(2.0f * (float)j / 256.0f, &s, &c);
        d_W256[j] = make_float2(c, -s);
    }
}

// ---------------- W pack ----------------
__global__ void pack_w_kernel(const float* __restrict__ wg, const float* __restrict__ wx) {
    int t = blockIdx.x * blockDim.x + threadIdx.x;
    if (t >= 4096) return;
    int wsel = t >> 11;
    int i = t & 2047;
    const float* W = wsel ? wx : wg;
    int lane = i & 31, kblk = (i >> 5) & 7, mblk = i >> 8;
    u32 qh[4], ql[4];
#pragma unroll
    for (int reg = 0; reg < 4; reg++) {
        int row = mblk * 16 + (lane >> 2) + 8 * (reg & 1);
        u32 hi = 0, lo = 0;
#pragma unroll
        for (int e = 0; e < 2; e++) {
            int k = kblk * 16 + (lane & 3) * 2 + e + 8 * (reg >> 1);
            float v = W[row * 128 + k];
            u32 hb, lb; sp_bits(v, hb, lb);
            hi |= hb << (16 * e); lo |= lb << (16 * e);
        }
        qh[reg] = hi; ql[reg] = lo;
    }
    d_WF[wsel][0][i] = (u64)qh[0] | ((u64)qh[1] << 32);
    d_WF[wsel][1][i] = (u64)ql[0] | ((u64)ql[1] << 32);
    d_WF[wsel][2][i] = (u64)qh[2] | ((u64)qh[3] << 32);
    d_WF[wsel][3][i] = (u64)ql[2] | ((u64)ql[3] << 32);
}

__device__ __forceinline__ float sigm(float v) { return 1.f / (1.f + expf(-v)); }

#define PIT  40
#define PITS 72
#define ASZ  (64 * PIT)
#define SSZ  (32 * PITS)

// ---------------- 1x1 conv — merged g/x launch ----------------
__global__ void __launch_bounds__(256, 2) conv_tc(
    const float* __restrict__ g, const float* __restrict__ x,
    const float* __restrict__ bg, const float* __restrict__ bx,
    float* __restrict__ yg, float* __restrict__ yx)
{
    __shared__ __nv_bfloat16 sXh[2][SSZ], sXl[2][SSZ];
    int z = blockIdx.z;
    int b = z & 1, wsel = z >> 1;
    const float* Xb = (wsel ? x : g) + (size_t)b * Cc * HWD;
    float* Yb = (wsel ? yx : yg) + (size_t)b * Cc * HWD;
    const float* bias = wsel ? bx : bg;
    int n0 = blockIdx.x * 64, m0 = blockIdx.y * 64;
    int t = threadIdx.x, lane = t & 31, wid = t >> 5;
    int wm = (wid >> 2) * 32, wn = (wid & 3) * 16;
    int g4 = lane >> 2, tc4 = lane & 3;

    float acc[2][2][4];
#pragma unroll
    for (int i = 0; i < 2; i++)
#pragma unroll
        for (int j = 0; j < 2; j++)
#pragma unroll
            for (int q = 0; q < 4; q++) acc[i][j][q] = 0.f;

    int kB = (lane & 7) + ((lane >> 3) & 1) * 8;
    int scB = t & 31, srB = t >> 5;
    int mblk_base = (m0 + wm) >> 4;

    float2 xv[4];
#define CONV_LOAD(K0) { \
    _Pragma("unroll") \
    for (int i = 0; i < 4; i++) \
        xv[i] = *(const float2*)&Xb[(size_t)((K0) + srB + i * 8) * HWD + n0 + 2 * scB]; }
#define CONV_STORE(BF) { \
    _Pragma("unroll") \
    for (int i = 0; i < 4; i++) { \
        u32 hi, lo; bsplit2(xv[i].x, xv[i].y, hi, lo); \
        int so = (srB + i * 8) * PITS + 2 * scB; \
        *(u32*)&sXh[BF][so] = hi; *(u32*)&sXl[BF][so] = lo; \
    } }

    CONV_LOAD(0)
    CONV_STORE(0)
    __syncthreads();
    for (int it = 0; it < 4; it++) {
        int buf = it & 1;
        if (it < 3) CONV_LOAD((it + 1) * 32)
        u32 aXh = smaddr(sXh[buf]), aXl = smaddr(sXl[buf]);
#pragma unroll
        for (int ks = 0; ks < 2; ks++) {
            int kb = ks * 16;
            int kblk = it * 2 + ks;
            u32 ah[2][4], al[2][4];
#pragma unroll
            for (int tm = 0; tm < 2; tm++) {
                size_t bi = ((size_t)((mblk_base + tm) * 8 + kblk) << 5) + lane;
                u64 v;
                v = d_WF[wsel][0][bi]; ah[tm][0] = (u32)v; ah[tm][1] = (u32)(v >> 32);
                v = d_WF[wsel][2][bi]; ah[tm][2] = (u32)v; ah[tm][3] = (u32)(v >> 32);
                v = d_WF[wsel][1][bi]; al[tm][0] = (u32)v; al[tm][1] = (u32)(v >> 32);
                v = d_WF[wsel][3][bi]; al[tm][2] = (u32)v; al[tm][3] = (u32)(v >> 32);
            }
            u32 bh[2][2], bl[2][2];
#pragma unroll
            for (int tn = 0; tn < 2; tn++) {
                u32 off = ((kb + kB) * PITS + wn + 8 * tn) * 2;
                ldmBT(bh[tn], aXh + off);
                ldmBT(bl[tn], aXl + off);
            }
#pragma unroll
            for (int tm = 0; tm < 2; tm++)
#pragma unroll
                for (int tn = 0; tn < 2; tn++) {
                    mma_bf16(acc[tm][tn], ah[tm], bh[tn]);
                    mma_bf16(acc[tm][tn], ah[tm], bl[tn]);
                    mma_bf16(acc[tm][tn], al[tm], bh[tn]);
                }
        }
        if (it < 3) CONV_STORE(buf ^ 1)
        __syncthreads();
    }
#undef CONV_LOAD
#undef CONV_STORE
#pragma unroll
    for (int tm = 0; tm < 2; tm++)
#pragma unroll
        for (int tn = 0; tn < 2; tn++) {
            int r0 = m0 + wm + 16 * tm + g4;
            int col = n0 + wn + 8 * tn + 2 * tc4;
            float bv0 = bias[r0], bv1 = bias[r0 + 8];
            *(float2*)&Yb[(size_t)r0 * HWD + col] =
                make_float2(acc[tm][tn][0] + bv0, acc[tm][tn][1] + bv0);
            *(float2*)&Yb[(size_t)(r0 + 8) * HWD + col] =
                make_float2(acc[tm][tn][2] + bv1, acc[tm][tn][3] + bv1);
        }
}

// ------- rfft along W — merged g/x launch -------
__global__ void __launch_bounds__(256, 2) rfftw_tc(
    const float* __restrict__ yg, const float* __restrict__ yx,
    float2* __restrict__ Fg, float2* __restrict__ Fx)
{
    __shared__ __nv_bfloat16 sAh[2][ASZ], sAl[2][ASZ];
    int z = blockIdx.z;
    int sel = z >> 8, bc = z & 255;
    const float* A = (sel ? yx : yg) + (size_t)bc * HWD;
    float2* Cp = (sel ? Fx : Fg) + (size_t)bc * Hh * WFD;
    int n0 = blockIdx.x * 64, m0 = blockIdx.y * 64;
    int t = threadIdx.x, lane = t & 31, wid = t >> 5;
    int wm = (wid >> 2) * 32, wn = (wid & 3) * 16;
    int g = lane >> 2, tc = lane & 3;

    float cre[2][2][4], cim[2][2][4];
#pragma unroll
    for (int i = 0; i < 2; i++)
#pragma unroll
        for (int j = 0; j < 2; j++)
#pragma unroll
            for (int q = 0; q < 4; q++) { cre[i][j][q] = 0.f; cim[i][j][q] = 0.f; }

    int lrA = lane & 15, lkA = (lane >> 4) * 8;
    int sc = t & 15, sr = t >> 4;
    int nblk0 = (n0 + wn) >> 3;

    float a0[4], a1[4];
#define RFW_LOAD(K0) { \
    _Pragma("unroll") \
    for (int i = 0; i < 4; i++) { \
        int r = sr + i * 16; int w = (K0) + 2 * sc; \
        if (w < Ww) { float2 t2 = *(const float2*)&A[(size_t)(m0 + r) * Ww + w]; \
                      a0[i] = t2.x; a1[i] = t2.y; } \
        else { a0[i] = 0.f; a1[i] = 0.f; } \
    } }
#define RFW_STORE(BF) { \
    _Pragma("unroll") \
    for (int i = 0; i < 4; i++) { \
        int so = (sr + i * 16) * PIT + 2 * sc; \
        u32 hi, lo; bsplit2(a0[i], a1[i], hi, lo); \
        *(u32*)&sAh[BF][so] = hi; *(u32*)&sAl[BF][so] = lo; \
    } }

    RFW_LOAD(0)
    RFW_STORE(0)
    __syncthreads();
    for (int it = 0; it < 16; it++) {
        int buf = it & 1;
        if (it < 15) RFW_LOAD((it + 1) * 32)
        u32 aAh = smaddr(sAh[buf]), aAl = smaddr(sAl[buf]);
#pragma unroll
        for (int ks = 0; ks < 2; ks++) {
            int kb = ks * 16;
            int kblk = it * 2 + ks;
            u32 ah[2][4], al[2][4];
#pragma unroll
            for (int tm = 0; tm < 2; tm++) {
                u32 off = ((wm + 16 * tm + lrA) * PIT + kb + lkA) * 2;
                ldmA(ah[tm], aAh + off);
                ldmA(al[tm], aAl + off);
            }
            u32 brh[2][2], brl[2][2], bih[2][2], bil[2][2];
#pragma unroll
            for (int tn = 0; tn < 2; tn++) {
                size_t bi = ((size_t)((nblk0 + tn) * 32 + kblk) << 5) + lane;
                u64 v;
                v = d_DwFrh[bi]; brh[tn][0] = (u32)v; brh[tn][1] = (u32)(v >> 32);
                v = d_DwFrl[bi]; brl[tn][0] = (u32)v; brl[tn][1] = (u32)(v >> 32);
                v = d_DwFih[bi]; bih[tn][0] = (u32)v; bih[tn][1] = (u32)(v >> 32);
                v = d_DwFil[bi]; bil[tn][0] = (u32)v; bil[tn][1] = (u32)(v >> 32);
            }
#pragma unroll
            for (int tm = 0; tm < 2; tm++)
#pragma unroll
                for (int tn = 0; tn < 2; tn++) {
                    mma_bf16(cre[tm][tn], ah[tm], brh[tn]);
                    mma_bf16(cre[tm][tn], ah[tm], brl[tn]);
                    mma_bf16(cre[tm][tn], al[tm], brh[tn]);
                    mma_bf16(cim[tm][tn], ah[tm], bih[tn]);
                    mma_bf16(cim[tm][tn], ah[tm], bil[tn]);
                    mma_bf16(cim[tm][tn], al[tm], bih[tn]);
                }
        }
        if (it < 15) RFW_STORE(buf ^ 1)
        __syncthreads();
    }
#undef RFW_LOAD
#undef RFW_STORE
#pragma unroll
    for (int tm = 0; tm < 2; tm++)
#pragma unroll
        for (int tn = 0; tn < 2; tn++) {
            int r0 = m0 + wm + 16 * tm + g;
            int col = n0 + wn + 8 * tn + 2 * tc;
            float4 v0 = make_float4(cre[tm][tn][0], cim[tm][tn][0], cre[tm][tn][1], cim[tm][tn][1]);
            *(float4*)&Cp[(size_t)r0 * WFD + col] = v0;
            float4 v1 = make_float4(cre[tm][tn][2], cim[tm][tn][2], cre[tm][tn][3], cim[tm][tn][3]);
            *(float4*)&Cp[(size_t)(r0 + 8) * WFD + col] = v1;
        }
}

// ------- irfft along W + residual -------
__global__ void __launch_bounds__(256, 2) irfft_add_tc(
    const float2* __restrict__ T, const float* __restrict__ x, float* __restrict__ r)
{
    __shared__ __nv_bfloat16 sArh[2][ASZ], sArl[2][ASZ], sAih[2][ASZ], sAil[2][ASZ];
    int bc = blockIdx.z;
    const float2* Ap = T + (size_t)bc * 65536;
    int n0 = blockIdx.x * 64, m0 = blockIdx.y * 64;
    int t = threadIdx.x, lane = t & 31, wid = t >> 5;
    int wm = (wid >> 2) * 32, wn = (wid & 3) * 16;
    int g = lane >> 2, tc = lane & 3;

    float acc[2][2][4];
#pragma unroll
    for (int i = 0; i < 2; i++)
#pragma unroll
        for (int j = 0; j < 2; j++)
#pragma unroll
            for (int q = 0; q < 4; q++) acc[i][j][q] = 0.f;

    int lrA = lane & 15, lkA = (lane >> 4) * 8;
    int sc = t & 15, sr = t >> 4;
    int nblk0 = (n0 + wn) >> 3;

    float4 va[4];
#define IRF_LOAD(K0) { \
    _Pragma("unroll") \
    for (int i = 0; i < 4; i++) { \
        int rr = sr + i * 16; \
        va[i] = *(const float4*)&Ap[(size_t)(m0 + rr) * 256 + (K0) + 2 * sc]; \
    } }
#define IRF_STORE(BF) { \
    _Pragma("unroll") \
    for (int i = 0; i < 4; i++) { \
        int so = (sr + i * 16) * PIT + 2 * sc; \
        u32 hi, lo; \
        bsplit2(va[i].x, va[i].z, hi, lo); \
        *(u32*)&sArh[BF][so] = hi; *(u32*)&sArl[BF][so] = lo; \
        bsplit2(va[i].y, va[i].w, hi, lo); \
        *(u32*)&sAih[BF][so] = hi; *(u32*)&sAil[BF][so] = lo; \
    } }

    IRF_LOAD(0)
    IRF_STORE(0)
    __syncthreads();
    for (int it = 0; it < 8; it++) {
        int buf = it & 1;
        if (it < 7) IRF_LOAD((it + 1) * 32)
        u32 aArh = smaddr(sArh[buf]), aArl = smaddr(sArl[buf]);
        u32 aAih = smaddr(sAih[buf]), aAil = smaddr(sAil[buf]);
#pragma unroll
        for (int ks = 0; ks < 2; ks++) {
            int kb = ks * 16;
            int kblk = it * 2 + ks;
            u32 arh[2][4], arl[2][4], aih[2][4], ail[2][4];
#pragma unroll
            for (int tm = 0; tm < 2; tm++) {
                u32 off = ((wm + 16 * tm + lrA) * PIT + kb + lkA) * 2;
                ldmA(arh[tm], aArh + off);
                ldmA(arl[tm], aArl + off);
                ldmA(aih[tm], aAih + off);
                ldmA(ail[tm], aAil + off);
            }
            u32 b1h[2][2], b1l[2][2], b2h[2][2], b2l[2][2];
#pragma unroll
            for (int tn = 0; tn < 2; tn++) {
                size_t bi = ((size_t)((nblk0 + tn) * 16 + kblk) << 5) + lane;
                u64 v;
                v = d_CwF1h[bi]; b1h[tn][0] = (u32)v; b1h[tn][1] = (u32)(v >> 32);
                v = d_CwF1l[bi]; b1l[tn][0] = (u32)v; b1l[tn][1] = (u32)(v >> 32);
                v = d_CwF2h[bi]; b2h[tn][0] = (u32)v; b2h[tn][1] = (u32)(v >> 32);
                v = d_CwF2l[bi]; b2l[tn][0] = (u32)v; b2l[tn][1] = (u32)(v >> 32);
            }
#pragma unroll
            for (int tm = 0; tm < 2; tm++)
#pragma unroll
                for (int tn = 0; tn < 2; tn++) {
                    mma_bf16(acc[tm][tn], arh[tm], b1h[tn]);
                    mma_bf16(acc[tm][tn], arh[tm], b1l[tn]);
                    mma_bf16(acc[tm][tn], arl[tm], b1h[tn]);
                    mma_bf16(acc[tm][tn], aih[tm], b2h[tn]);
                    mma_bf16(acc[tm][tn], aih[tm], b2l[tn]);
                    mma_bf16(acc[tm][tn], ail[tm], b2h[tn]);
                }
        }
        if (it < 7) IRF_STORE(buf ^ 1)
        __syncthreads();
    }
#undef IRF_LOAD
#undef IRF_STORE
#pragma unroll
    for (int tm = 0; tm < 2; tm++)
#pragma unroll
        for (int tn = 0; tn < 2; tn++) {
            int col = n0 + wn + 8 * tn + 2 * tc;
            if (col < Ww) {
                int r0 = m0 + wm + 16 * tm + g;
                size_t i0 = (size_t)bc * HWD + (size_t)r0 * Ww + col;
                size_t i1 = i0 + (size_t)8 * Ww;
                float2 xv = *(const float2*)&x[i0];
                *(float2*)&r[i0] = make_float2(acc[tm][tn][0] + xv.x, acc[tm][tn][1] + xv.y);
                xv = *(const float2*)&x[i1];
                *(float2*)&r[i1] = make_float2(acc[tm][tn][2] + xv.x, acc[tm][tn][3] + xv.y);
            }
        }
}

// ---------------- forward ffth (merged g/x) + fused variance partials ------
__global__ void __launch_bounds__(256) ffth_fwd(
    const float2* __restrict__ Fg, const float2* __restrict__ Fx,
    float2* __restrict__ Gg, float2* __restrict__ Gx,
    const float2* __restrict__ fg, const float2* __restrict__ fx,
    float* __restrict__ vp)
{
    __shared__ float2 Xs[256][17];
    __shared__ float2 Ws[256];
    int yz = blockIdx.y;
    int sel = yz >> 8, bc = yz & 255;
    const float2* inp = (sel ? Fx : Fg) + (size_t)bc * 65536;
    float2* outp = (sel ? Gx : Gg) + (size_t)bc * 65536;
    const float2* filt = sel ? fx : fg;
    int v0 = blockIdx.x * 16;
    int tx = threadIdx.x;
    int ty = threadIdx.y;
    int t = ty * 16 + tx;

    {
        float2 w = d_W256[t];
        Ws[t] = w;
    }
#pragma unroll
    for (int i = 0; i < 16; i++) {
        int h = i * 16 + ty;
        Xs[h][tx] = inp[(size_t)h * 256 + v0 + tx];
    }
    __syncthreads();

    float2 rr[16];
    {
        u64 tw[16];
#pragma unroll
        for (int n1 = 0; n1 < 16; n1++) {
            float2 w = Ws[(n1 * ty * 16) & 255];
            tw[n1] = pk2(w.x, w.y);
        }
#pragma unroll
        for (int n2 = 0; n2 < 16; n2++) {
            u64 accA = 0ull, accB = 0ull;
#pragma unroll
            for (int n1 = 0; n1 < 16; n1++) {
                float2 xv = Xs[16 * n1 + n2][tx];
                u64 xp = pk2(xv.x, xv.y);
                u64 xq = pk2(xv.y, xv.x);
                accA = ffma2(xp, tw[n1], accA);
                accB = ffma2(xq, tw[n1], accB);
            }
            float2 a = up2(accA), b = up2(accB);
            float ar = a.x - a.y, ai = b.x + b.y;
            float2 tm = Ws[(n2 * ty) & 255];
            rr[n2] = make_float2(ar * tm.x - ai * tm.y, ar * tm.y + ai * tm.x);
        }
    }
    __syncthreads();
#pragma unroll
    for (int n2 = 0; n2 < 16; n2++)
        Xs[ty * 16 + n2][tx] = rr[n2];
    __syncthreads();

    {
        u64 tw[16];
#pragma unroll
        for (int n2 = 0; n2 < 16; n2++) {
            float2 w = Ws[(n2 * ty * 16) & 255];
            tw[n2] = pk2(w.x, w.y);
        }
        int c = bc & (Cc - 1);
#pragma unroll
        for (int k1 = 0; k1 < 16; k1++) {
            u64 accA = 0ull, accB = 0ull;
#pragma unroll
            for (int n2 = 0; n2 < 16; n2++) {
                float2 xv = Xs[k1 * 16 + n2][tx];
                u64 xp = pk2(xv.x, xv.y);
                u64 xq = pk2(xv.y, xv.x);
                accA = ffma2(xp, tw[n2], accA);
                accB = ffma2(xq, tw[n2], accB);
            }
            float2 a = up2(accA), b = up2(accB);
            int u = k1 + 16 * ty;
            float2 v = make_float2((a.x - a.y) * 0.0625f, (b.x + b.y) * 0.0625f);
            float2 wc = filt[((size_t)c * Hh + u) * WFD + v0 + tx];
            v = make_float2(v.x * wc.x - v.y * wc.y, v.x * wc.y + v.y * wc.x);
            outp[(size_t)u * 256 + v0 + tx] = v;
            if (sel == 0) {
                // deterministic width-16 xor-tree reduction over tx
                float sre = v.x, sim = v.y, ssq = v.x * v.x + v.y * v.y;
#pragma unroll
                for (int msk = 8; msk >= 1; msk >>= 1) {
                    sre += __shfl_xor_sync(0xFFFFFFFFu, sre, msk);
                    sim += __shfl_xor_sync(0xFFFFFFFFu, sim, msk);
                    ssq += __shfl_xor_sync(0xFFFFFFFFu, ssq, msk);
                }
                if (tx == 0) {
                    size_t idx = (((size_t)bc * 256 + u) * 16 + blockIdx.x) * 4;
                    *(float4*)&vp[idx] = make_float4(sre, sim, ssq, 0.f);
                }
            }
        }
    }
}

// ------- variance finalize -------
__global__ void var_fin(const float* __restrict__ vp, float* __restrict__ rsq)
{
    int row = blockIdx.x * 256 + threadIdx.x;   // < 65536
    const float4* p = (const float4*)(vp + (size_t)row * 64);
    float sre = 0.f, sim = 0.f, ssq = 0.f;
#pragma unroll
    for (int i = 0; i < 16; i++) {
        float4 v = p[i];
        sre += v.x; sim += v.y; ssq += v.z;
    }
    float mr = sre * (1.f / 256.f), mi = sim * (1.f / 256.f);
    float var = ssq * (1.f / 256.f) - mr * mr - mi * mi;
    rsq[row] = 1.f / sqrtf(6.283185307179586f * var);
}

// ---------------- inverse ffth ----------------
__global__ void __launch_bounds__(256) ffth_inv(
    const float2* __restrict__ in, float2* __restrict__ out)
{
    __shared__ float2 Xs[256][17];
    __shared__ float2 Ws[256];
    int bc = blockIdx.y;
    int v0 = blockIdx.x * 16;
    int tx = threadIdx.x;
    int ty = threadIdx.y;
    int t = ty * 16 + tx;
    const float2* inp = in + (size_t)bc * 65536 + v0;
    float2* outp = out + (size_t)bc * 65536 + v0;

    {
        float2 w = d_W256[t];
        w.y = -w.y;
        Ws[t] = w;
    }
#pragma unroll
    for (int i = 0; i < 16; i++) {
        int h = i * 16 + ty;
        Xs[h][tx] = inp[(size_t)h * 256 + tx];
    }
    __syncthreads();

    float2 rr[16];
    {
        u64 tw[16];
#pragma unroll
        for (int n1 = 0; n1 < 16; n1++) {
            float2 w = Ws[(n1 * ty * 16) & 255];
            tw[n1] = pk2(w.x, w.y);
        }
#pragma unroll
        for (int n2 = 0; n2 < 16; n2++) {
            u64 accA = 0ull, accB = 0ull;
#pragma unroll
            for (int n1 = 0; n1 < 16; n1++) {
                float2 xv = Xs[16 * n1 + n2][tx];
                u64 xp = pk2(xv.x, xv.y);
                u64 xq = pk2(xv.y, xv.x);
                accA = ffma2(xp, tw[n1], accA);
                accB = ffma2(xq, tw[n1], accB);
            }
            float2 a = up2(accA), b = up2(accB);
            float ar = a.x - a.y, ai = b.x + b.y;
            float2 tm = Ws[(n2 * ty) & 255];
            rr[n2] = make_float2(ar * tm.x - ai * tm.y, ar * tm.y + ai * tm.x);
        }
    }
    __syncthreads();
#pragma unroll
    for (int n2 = 0; n2 < 16; n2++)
        Xs[ty * 16 + n2][tx] = rr[n2];
    __syncthreads();

    {
        u64 tw[16];
#pragma unroll
        for (int n2 = 0; n2 < 16; n2++) {
            float2 w = Ws[(n2 * ty * 16) & 255];
            tw[n2] = pk2(w.x, w.y);
        }
#pragma unroll
        for (int k1 = 0; k1 < 16; k1++) {
            u64 accA = 0ull, accB = 0ull;
#pragma unroll
            for (int n2 = 0; n2 < 16; n2++) {
                float2 xv = Xs[k1 * 16 + n2][tx];
                u64 xp = pk2(xv.x, xv.y);
                u64 xq = pk2(xv.y, xv.x);
                accA = ffma2(xp, tw[n2], accA);
                accB = ffma2(xq, tw[n2], accB);
            }
            float2 a = up2(accA), b = up2(accB);
            int u = k1 + 16 * ty;
            float2 v = make_float2((a.x - a.y) * 0.0625f, (b.x + b.y) * 0.0625f);
            outp[(size_t)u * 256 + tx] = v;
        }
    }
}

// ------- scores — HMMA complex, double-buffered (dynamic smem) -------
__global__ void __launch_bounds__(256) scores_tc(
    const float2* __restrict__ Gb, const float2* __restrict__ Xb,
    const float* __restrict__ rsq, float2* __restrict__ Sb)
{
    extern __shared__ __nv_bfloat16 dynS[];
    __nv_bfloat16* sGrh = dynS;
    __nv_bfloat16* sGrl = sGrh + 2 * SSZ;
    __nv_bfloat16* sGih = sGrl + 2 * SSZ;
    __nv_bfloat16* sGil = sGih + 2 * SSZ;
    __nv_bfloat16* sXrh = sGil + 2 * SSZ;
    __nv_bfloat16* sXrl = sXrh + 2 * SSZ;
    __nv_bfloat16* sXih = sXrl + 2 * SSZ;
    __nv_bfloat16* sXil = sXih + 2 * SSZ;
    int bc = blockIdx.z;
    const float2* Ap = Gb + (size_t)bc * 65536;
    const float2* Bp = Xb + (size_t)bc * 65536;
    float2* Cp = Sb + (size_t)bc * 65536;
    int n0 = blockIdx.x * 64, m0 = blockIdx.y * 64;
    int t = threadIdx.x, lane = t & 31, wid = t >> 5;
    int wm = (wid >> 2) * 32, wn = (wid & 3) * 16;
    int g = lane >> 2, tc4 = lane & 3;

    float are[2][2][4], aim[2][2][4];
#pragma unroll
    for (int i = 0; i < 2; i++)
#pragma unroll
        for (int j = 0; j < 2; j++)
#pragma unroll
            for (int q = 0; q < 4; q++) { are[i][j][q] = 0.f; aim[i][j][q] = 0.f; }

    int kA = (lane & 7) + ((lane >> 4) & 1) * 8;
    int mA = ((lane >> 3) & 1) * 8;
    int kB = (lane & 7) + ((lane >> 3) & 1) * 8;
    int sc = t & 31, sr = t >> 5;

    float4 vA[4], vB[4];
#define SCR_LOAD(K0) { \
    _Pragma("unroll") \
    for (int i = 0; i < 4; i++) { \
        int k = sr + i * 8; \
        vA[i] = *(const float4*)&Ap[(size_t)((K0) + k) * 256 + m0 + 2 * sc]; \
        vB[i] = *(const float4*)&Bp[(size_t)((K0) + k) * 256 + n0 + 2 * sc]; \
    } }
#define SCR_STORE(BF) { \
    _Pragma("unroll") \
    for (int i = 0; i < 4; i++) { \
        int so = (BF) * SSZ + (sr + i * 8) * PITS + 2 * sc; \
        u32 hi, lo; \
        bsplit2(vA[i].x, vA[i].z, hi, lo); *(u32*)&sGrh[so] = hi; *(u32*)&sGrl[so] = lo; \
        bsplit2(vA[i].y, vA[i].w, hi, lo); *(u32*)&sGih[so] = hi; *(u32*)&sGil[so] = lo; \
        bsplit2(vB[i].x, vB[i].z, hi, lo); *(u32*)&sXrh[so] = hi; *(u32*)&sXrl[so] = lo; \
        bsplit2(vB[i].y, vB[i].w, hi, lo); *(u32*)&sXih[so] = hi; *(u32*)&sXil[so] = lo; \
    } }

    SCR_LOAD(0)
    SCR_STORE(0)
    __syncthreads();
    for (int it = 0; it < 8; it++) {
        int buf = it & 1;
        if (it < 7) SCR_LOAD((it + 1) * 32)
        u32 aGrh = smaddr(sGrh + buf * SSZ), aGrl = smaddr(sGrl + buf * SSZ);
        u32 aGih = smaddr(sGih + buf * SSZ), aGil = smaddr(sGil + buf * SSZ);
        u32 aXrh = smaddr(sXrh + buf * SSZ), aXrl = smaddr(sXrl + buf * SSZ);
        u32 aXih = smaddr(sXih + buf * SSZ), aXil = smaddr(sXil + buf * SSZ);
#pragma unroll
        for (int ks = 0; ks < 2; ks++) {
            int kb = ks * 16;
            u32 grh[2][4], grl[2][4], gih[2][4], gil[2][4];
#pragma unroll
            for (int tm = 0; tm < 2; tm++) {
                u32 off = ((kb + kA) * PITS + wm + 16 * tm + mA) * 2;
                ldmAT(grh[tm], aGrh + off);
                ldmAT(grl[tm], aGrl + off);
                ldmAT(gih[tm], aGih + off);
                ldmAT(gil[tm], aGil + off);
            }
            u32 xrh[2][2], xrl[2][2], xih[2][2], xil[2][2];
#pragma unroll
            for (int tn = 0; tn < 2; tn++) {
                u32 off = ((kb + kB) * PITS + wn + 8 * tn) * 2;
                ldmBT(xrh[tn], aXrh + off);
                ldmBT(xrl[tn], aXrl + off);
                ldmBT(xih[tn], aXih + off);
                ldmBT(xil[tn], aXil + off);
            }
#pragma unroll
            for (int tm = 0; tm < 2; tm++) {
                u32 nih[4], nil_[4];
#pragma unroll
                for (int q = 0; q < 4; q++) {
                    nih[q]  = gih[tm][q] ^ 0x80008000u;
                    nil_[q] = gil[tm][q] ^ 0x80008000u;
                }
#pragma unroll
                for (int tn = 0; tn < 2; tn++) {
                    mma_bf16(are[tm][tn], grh[tm], xrh[tn]);
                    mma_bf16(are[tm][tn], grh[tm], xrl[tn]);
                    mma_bf16(are[tm][tn], grl[tm], xrh[tn]);
                    mma_bf16(are[tm][tn], nih,     xih[tn]);
                    mma_bf16(are[tm][tn], nih,     xil[tn]);
                    mma_bf16(are[tm][tn], nil_,    xih[tn]);
                    mma_bf16(aim[tm][tn], grh[tm], xih[tn]);
                    mma_bf16(aim[tm][tn], grh[tm], xil[tn]);
                    mma_bf16(aim[tm][tn], grl[tm], xih[tn]);
                    mma_bf16(aim[tm][tn], gih[tm], xrh[tn]);
                    mma_bf16(aim[tm][tn], gih[tm], xrl[tn]);
                    mma_bf16(aim[tm][tn], gil[tm], xrh[tn]);
                }
            }
        }
        if (it < 7) SCR_STORE(buf ^ 1)
        __syncthreads();
    }
#undef SCR_LOAD
#undef SCR_STORE
#pragma unroll
    for (int tm = 0; tm < 2; tm++)
#pragma unroll
        for (int tn = 0; tn < 2; tn++) {
            int r0 = m0 + wm + 16 * tm + g;
            int col = n0 + wn + 8 * tn + 2 * tc4;
            float s0 = rsq[bc * Hh + r0], s1 = rsq[bc * Hh + r0 + 8];
            float4 o0 = make_float4(
                sigm(are[tm][tn][0] * s0), sigm(aim[tm][tn][0] * s0),
                sigm(are[tm][tn][1] * s0), sigm(aim[tm][tn][1] * s0));
            *(float4*)&Cp[(size_t)r0 * 256 + col] = o0;
            float4 o1 = make_float4(
                sigm(are[tm][tn][2] * s1), sigm(aim[tm][tn][2] * s1),
                sigm(are[tm][tn][3] * s1), sigm(aim[tm][tn][3] * s1));
            *(float4*)&Cp[(size_t)(r0 + 8) * 256 + col] = o1;
        }
}

// ------- channel LayerNorm — float4 smem-tiled, 128w per block -------
#define LN_SMEM ((128 * 32 + 2 * 8 * 32 + 64) * 16)
__global__ void __launch_bounds__(256) ln_kernel(
    const float* __restrict__ r, const float* __restrict__ gamma,
    const float* __restrict__ beta, float* __restrict__ out)
{
    extern __shared__ float4 lns[];
    float4* tile = lns;               // [128][32]
    float4* ps   = tile + 128 * 32;   // [8][32]
    float4* qs   = ps + 8 * 32;       // [8][32]
    float4* muv  = qs + 8 * 32;       // [32]
    float4* invv = muv + 32;          // [32]
    int blk = blockIdx.x;
    int b = blk / 1020;
    int w0 = (blk - b * 1020) * 128;
    int t = threadIdx.x;
    int w4 = t & 31, cq = t >> 5;

    float4 s = make_float4(0.f, 0.f, 0.f, 0.f);
    float4 q = make_float4(0.f, 0.f, 0.f, 0.f);
#pragma unroll
    for (int c0 = 0; c0 < 128; c0 += 8) {
        int c = c0 + cq;
        float4 v = *(const float4*)&r[(size_t)(b * Cc + c) * HWD + w0 + w4 * 4];
        tile[c * 32 + w4] = v;
        s.x += v.x; s.y += v.y; s.z += v.z; s.w += v.w;
        q.x += v.x * v.x; q.y += v.y * v.y; q.z += v.z * v.z; q.w += v.w * v.w;
    }
    ps[cq * 32 + w4] = s;
    qs[cq * 32 + w4] = q;
    __syncthreads();
    if (t < 32) {
        float4 S = make_float4(0.f, 0.f, 0.f, 0.f);
        float4 Q = make_float4(0.f, 0.f, 0.f, 0.f);
#pragma unroll
        for (int i = 0; i < 8; i++) {
            float4 a = ps[i * 32 + t];
            S.x += a.x; S.y += a.y; S.z += a.z; S.w += a.w;
            a = qs[i * 32 + t];
            Q.x += a.x; Q.y += a.y; Q.z += a.z; Q.w += a.w;
        }
        float4 m = make_float4(S.x * (1.f / 128.f), S.y * (1.f / 128.f),
                               S.z * (1.f / 128.f), S.w * (1.f / 128.f));
        float4 iv;
        iv.x = rsqrtf(Q.x * (1.f / 128.f) - m.x * m.x + 1e-6f);
        iv.y = rsqrtf(Q.y * (1.f / 128.f) - m.y * m.y + 1e-6f);
        iv.z = rsqrtf(Q.z * (1.f / 128.f) - m.z * m.z + 1e-6f);
        iv.w = rsqrtf(Q.w * (1.f / 128.f) - m.w * m.w + 1e-6f);
        muv[t] = m;
        invv[t] = iv;
    }
    __syncthreads();
    float4 m = muv[w4], iv = invv[w4];
#pragma unroll
    for (int c0 = 0; c0 < 128; c0 += 8) {
        int c = c0 + cq;
        float4 v = tile[c * 32 + w4];
        float gm = gamma[c], bt = beta[c];
        float4 o;
        o.x = gm * (v.x - m.x) * iv.x + bt;
        o.y = gm * (v.y - m.y) * iv.y + bt;
        o.z = gm * (v.z - m.z) * iv.z + bt;
        o.w = gm * (v.w - m.w) * iv.w + bt;
        *(float4*)&out[(size_t)(b * Cc + c) * HWD + w0 + w4 * 4] = o;
    }
}

// ---------------- launch ----------------
extern "C" void kernel_launch(void* const* d_in, const int* in_sizes, int n_in,
                              void* d_out, int out_size)
{
    (void)in_sizes; (void)n_in; (void)out_size;
    const float*  g     = (const float*)d_in[0];
    const float*  x     = (const float*)d_in[1];
    const float*  wg    = (const float*)d_in[2];
    const float*  bg    = (const float*)d_in[3];
    const float*  wx    = (const float*)d_in[4];
    const float*  bx    = (const float*)d_in[5];
    const float2* fg    = (const float2*)d_in[6];
    const float2* fx    = (const float2*)d_in[7];
    const float*  gamma = (const float*)d_in[8];
    const float*  beta  = (const float*)d_in[9];
    float* out = (float*)d_out;

    float *yg, *yx, *rb, *rsq, *vp;
    float2 *Fg, *Fx, *Gg, *Gx, *S, *T;
    cudaGetSymbolAddress((void**)&yg,  d_yg);
    cudaGetSymbolAddress((void**)&yx,  d_yx);
    cudaGetSymbolAddress((void**)&Fg,  d_Fg);
    cudaGetSymbolAddress((void**)&Fx,  d_Fx);
    cudaGetSymbolAddress((void**)&Gg,  d_Gg);
    cudaGetSymbolAddress((void**)&Gx,  d_Gx);
    cudaGetSymbolAddress((void**)&S,   d_Sb);
    cudaGetSymbolAddress((void**)&T,   d_Tb);
    cudaGetSymbolAddress((void**)&rb,  d_rb);
    cudaGetSymbolAddress((void**)&rsq, d_rsq);
    cudaGetSymbolAddress((void**)&vp,  d_vp);

    static int attr_done = 0;
    if (!attr_done) {
        cudaFuncSetAttribute(scores_tc, cudaFuncAttributeMaxDynamicSharedMemorySize,
                             16 * SSZ * 2);
        cudaFuncSetAttribute(ln_kernel, cudaFuncAttributeMaxDynamicSharedMemorySize,
                             LN_SMEM);
        attr_done = 1;
    }

    dim3 blk(16, 16);

    build_tables_kernel<<<512, 256>>>();
    pack_w_kernel<<<16, 256>>>(wg, wx);

    conv_tc<<<dim3(HWD / 64, 2, 2 * Bb), 256>>>(g, x, bg, bx, yg, yx);

    rfftw_tc<<<dim3(4, 4, 2 * BCD), 256>>>(yg, yx, Fg, Fx);

    ffth_fwd<<<dim3(16, 2 * BCD), blk>>>(Fg, Fx, Gg, Gx, fg, fx, vp);

    var_fin<<<BCD * Hh / 256, 256>>>(vp, rsq);

    scores_tc<<<dim3(4, 4, BCD), 256, 16 * SSZ * 2>>>(Gg, Gx, rsq, S);

    ffth_inv<<<dim3(16, BCD), blk>>>(S, T);

    irfft_add_tc<<<dim3(8, 4, BCD), 256>>>(T, x, rb);

    ln_kernel<<<Bb * 1020, 256, LN_SMEM>>>(rb, gamma, beta, out);
}